// round 2
// baseline (speedup 1.0000x reference)
#include <cuda_runtime.h>
#include <cuda_bf16.h>
#include <cstdint>

// Problem constants
constexpr int NN   = 50000;   // nodes
constexpr int NE   = 640000;  // edges
constexpr int RR   = 3;       // relations
constexpr int EMB  = 64;
constexpr int HID  = 128;
constexpr int NCLS = 4;
constexpr int GG   = 512;     // graphs
constexpr int IN_DIM = 2 * EMB + 1;   // 129
constexpr int LDA1  = 136;            // padded K for layer 1 (multiple of 8, float4-aligned rows)

// ---------------- scratch (static device globals; no allocation at runtime) ---------
__device__ float g_X1[(size_t)NN * LDA1];          // layer-1 input, padded [N,136]
__device__ float g_Y1[(size_t)4 * NN * HID];       // y0|y1|y2|h1 sections
__device__ float g_Y2[(size_t)4 * NN * HID];       // y0|y1|y2|h2 sections
__device__ int   g_cnt[RR * NN];
__device__ float g_inv[RR * NN];
__device__ float g_pool[GG * HID];
__device__ int   g_gcnt[GG];

// ---------------- small kernels ------------------------------------------------------

__global__ void zero_misc_kernel() {
    int i = blockIdx.x * blockDim.x + threadIdx.x;
    if (i < RR * NN) g_cnt[i] = 0;
    if (i < GG * HID) g_pool[i] = 0.f;
    if (i < GG) g_gcnt[i] = 0;
}

__global__ void count_edges_kernel(const int* __restrict__ ei, const int* __restrict__ et) {
    int e = blockIdx.x * blockDim.x + threadIdx.x;
    if (e >= NE) return;
    int dst = ei[NE + e];
    int r   = et[e];
    atomicAdd(&g_cnt[r * NN + dst], 1);
}

__global__ void make_inv_kernel() {
    int i = blockIdx.x * blockDim.x + threadIdx.x;
    if (i >= RR * NN) return;
    int c = g_cnt[i];
    g_inv[i] = 1.f / (float)(c > 0 ? c : 1);
}

__global__ void build_x1_kernel(const float* __restrict__ pos,
                                const int* __restrict__ sid,
                                const int* __restrict__ cid,
                                const float* __restrict__ se,
                                const float* __restrict__ ce) {
    int idx = blockIdx.x * blockDim.x + threadIdx.x;
    if (idx >= NN * LDA1) return;
    int n = idx / LDA1;
    int j = idx - n * LDA1;
    float v;
    if (j < 64)       v = se[sid[n] * 64 + j];
    else if (j < 128) v = ce[cid[n] * 64 + (j - 64)];
    else if (j == 128) v = pos[n];
    else               v = 0.f;
    g_X1[idx] = v;
}

// ---------------- fused 4-way SGEMM: Y[:, nt*128:(nt+1)*128] = A @ B_nt (+bias if nt==3)
// BM=BN=128, BK=8, 256 threads, 8x8 microtile.
__global__ void __launch_bounds__(256) gemm_rgcn_kernel(
    const float* __restrict__ A, int lda, int K, int KT,
    const float* __restrict__ W,      // [R, K, 128] contiguous
    const float* __restrict__ root,   // [K, 128]
    const float* __restrict__ bias,   // [128]
    float* __restrict__ Y)            // [4, N, 128] sections
{
    __shared__ float As[8][128];
    __shared__ float Bs[8][128];

    const int nt = blockIdx.y;
    const float* B = (nt < 3) ? (W + (size_t)nt * K * HID) : root;
    float* C = Y + (size_t)nt * NN * HID;

    const int m0  = blockIdx.x * 128;
    const int tid = threadIdx.x;

    const int a_row  = tid >> 1;          // 0..127
    const int a_col4 = (tid & 1) * 4;     // 0 or 4
    const int b_row  = tid >> 5;          // 0..7
    const int b_col4 = (tid & 31) * 4;    // 0..124

    const int tm = (tid >> 4) * 8;
    const int tn = (tid & 15) * 8;

    float acc[8][8] = {};

    const int  grow    = m0 + a_row;
    const bool arow_ok = (grow < NN);
    const float* Arow  = A + (size_t)grow * lda;

    for (int kt = 0; kt < KT; kt++) {
        const int k0 = kt * 8;
        float4 av = make_float4(0.f, 0.f, 0.f, 0.f);
        if (arow_ok) av = *reinterpret_cast<const float4*>(Arow + k0 + a_col4);
        As[a_col4 + 0][a_row] = av.x;
        As[a_col4 + 1][a_row] = av.y;
        As[a_col4 + 2][a_row] = av.z;
        As[a_col4 + 3][a_row] = av.w;

        float4 bv = make_float4(0.f, 0.f, 0.f, 0.f);
        const int kb = k0 + b_row;
        if (kb < K) bv = *reinterpret_cast<const float4*>(B + (size_t)kb * HID + b_col4);
        *reinterpret_cast<float4*>(&Bs[b_row][b_col4]) = bv;

        __syncthreads();

        #pragma unroll
        for (int k = 0; k < 8; k++) {
            float ar[8], br[8];
            #pragma unroll
            for (int i = 0; i < 8; i++) ar[i] = As[k][tm + i];
            #pragma unroll
            for (int j = 0; j < 8; j++) br[j] = Bs[k][tn + j];
            #pragma unroll
            for (int i = 0; i < 8; i++)
                #pragma unroll
                for (int j = 0; j < 8; j++)
                    acc[i][j] += ar[i] * br[j];
        }
        __syncthreads();
    }

    #pragma unroll
    for (int i = 0; i < 8; i++) {
        const int row = m0 + tm + i;
        if (row >= NN) break;
        #pragma unroll
        for (int j = 0; j < 8; j += 4) {
            float4 v = make_float4(acc[i][j], acc[i][j + 1], acc[i][j + 2], acc[i][j + 3]);
            if (nt == 3) {
                v.x += bias[tn + j];
                v.y += bias[tn + j + 1];
                v.z += bias[tn + j + 2];
                v.w += bias[tn + j + 3];
            }
            *reinterpret_cast<float4*>(C + (size_t)row * HID + tn + j) = v;
        }
    }
}

// ---------------- edge scatter: warp per edge, vector f32 atomics --------------------
__global__ void edge_scatter_kernel(const int* __restrict__ ei,
                                    const int* __restrict__ et,
                                    const float* __restrict__ Ybase,  // y sections [3, N, 128]
                                    float* __restrict__ out) {        // h section  [N, 128]
    const int w = (blockIdx.x * blockDim.x + threadIdx.x) >> 5;
    if (w >= NE) return;
    const int lane = threadIdx.x & 31;
    const int src = ei[w];
    const int dst = ei[NE + w];
    const int r   = et[w];
    const float s = g_inv[r * NN + dst];
    float4 v = *reinterpret_cast<const float4*>(
        Ybase + ((size_t)r * NN + src) * HID + lane * 4);
    v.x *= s; v.y *= s; v.z *= s; v.w *= s;
    float* o = out + (size_t)dst * HID + lane * 4;
    asm volatile("red.global.add.v4.f32 [%0], {%1, %2, %3, %4};"
                 :: "l"(o), "f"(v.x), "f"(v.y), "f"(v.z), "f"(v.w) : "memory");
}

__global__ void relu_inplace_kernel(float* __restrict__ p, int n) {
    int i = blockIdx.x * blockDim.x + threadIdx.x;
    if (i < n) p[i] = fmaxf(p[i], 0.f);
}

// ---------------- pooling: warp per node, relu fused on read -------------------------
__global__ void pool_kernel(const int* __restrict__ batch, const float* __restrict__ h2) {
    const int w = (blockIdx.x * blockDim.x + threadIdx.x) >> 5;
    if (w >= NN) return;
    const int lane = threadIdx.x & 31;
    const int g = batch[w];
    float4 v = *reinterpret_cast<const float4*>(h2 + (size_t)w * HID + lane * 4);
    v.x = fmaxf(v.x, 0.f); v.y = fmaxf(v.y, 0.f);
    v.z = fmaxf(v.z, 0.f); v.w = fmaxf(v.w, 0.f);
    float* o = g_pool + (size_t)g * HID + lane * 4;
    asm volatile("red.global.add.v4.f32 [%0], {%1, %2, %3, %4};"
                 :: "l"(o), "f"(v.x), "f"(v.y), "f"(v.z), "f"(v.w) : "memory");
    if (lane == 0) atomicAdd(&g_gcnt[g], 1);
}

__global__ void final_kernel(const float* __restrict__ lw, const float* __restrict__ lb,
                             float* __restrict__ out) {
    int g = blockIdx.x * blockDim.x + threadIdx.x;
    if (g >= GG) return;
    const int c = g_gcnt[g];
    const float inv = 1.f / (float)(c > 0 ? c : 1);
    float a0 = 0.f, a1 = 0.f, a2 = 0.f, a3 = 0.f;
    const float* p = g_pool + (size_t)g * HID;
    #pragma unroll 8
    for (int k = 0; k < HID; k++) {
        float v = p[k] * inv;
        a0 += v * lw[k * 4 + 0];
        a1 += v * lw[k * 4 + 1];
        a2 += v * lw[k * 4 + 2];
        a3 += v * lw[k * 4 + 3];
    }
    out[g * 4 + 0] = a0 + lb[0];
    out[g * 4 + 1] = a1 + lb[1];
    out[g * 4 + 2] = a2 + lb[2];
    out[g * 4 + 3] = a3 + lb[3];
}

// ---------------- launch --------------------------------------------------------------
extern "C" void kernel_launch(void* const* d_in, const int* in_sizes, int n_in,
                              void* d_out, int out_size) {
    const float* pos      = (const float*)d_in[0];
    const int*   shape_id = (const int*)  d_in[1];
    const int*   color_id = (const int*)  d_in[2];
    const int*   ei       = (const int*)  d_in[3];   // [2, E]
    const int*   et       = (const int*)  d_in[4];   // [E]
    const int*   batch    = (const int*)  d_in[5];   // [N]
    const float* se       = (const float*)d_in[6];   // [16, 64]
    const float* ce       = (const float*)d_in[7];   // [16, 64]
    const float* W1       = (const float*)d_in[8];   // [3, 129, 128]
    const float* root1    = (const float*)d_in[9];   // [129, 128]
    const float* b1       = (const float*)d_in[10];  // [128]
    const float* W2       = (const float*)d_in[11];  // [3, 128, 128]
    const float* root2    = (const float*)d_in[12];  // [128, 128]
    const float* b2       = (const float*)d_in[13];  // [128]
    const float* lin_w    = (const float*)d_in[14];  // [128, 4]
    const float* lin_b    = (const float*)d_in[15];  // [4]
    float* out = (float*)d_out;                      // [512, 4]

    float* X1 = nullptr; float* Y1 = nullptr; float* Y2 = nullptr;
    cudaGetSymbolAddress((void**)&X1, g_X1);
    cudaGetSymbolAddress((void**)&Y1, g_Y1);
    cudaGetSymbolAddress((void**)&Y2, g_Y2);

    const int TB = 256;

    // 0) zero counters / pool
    zero_misc_kernel<<<(RR * NN + TB - 1) / TB, TB>>>();
    // 1) edge counts + reciprocals (shared across both layers)
    count_edges_kernel<<<(NE + TB - 1) / TB, TB>>>(ei, et);
    make_inv_kernel<<<(RR * NN + TB - 1) / TB, TB>>>();
    // 2) build layer-1 input features (padded)
    build_x1_kernel<<<(NN * LDA1 + TB - 1) / TB, TB>>>(pos, shape_id, color_id, se, ce);

    dim3 gemm_grid((NN + 127) / 128, 4);
    // 3) layer 1: fused [W1_0|W1_1|W1_2|root1] GEMM
    gemm_rgcn_kernel<<<gemm_grid, 256>>>(X1, LDA1, IN_DIM, LDA1 / 8, W1, root1, b1, Y1);
    // 4) layer 1 edge aggregation into h1
    edge_scatter_kernel<<<(NE * 32 + TB - 1) / TB, TB>>>(ei, et, Y1, Y1 + (size_t)3 * NN * HID);
    // 5) relu(h1) in place -> X2
    relu_inplace_kernel<<<(NN * HID + TB - 1) / TB, TB>>>(Y1 + (size_t)3 * NN * HID, NN * HID);
    // 6) layer 2 GEMM on X2
    gemm_rgcn_kernel<<<gemm_grid, 256>>>(Y1 + (size_t)3 * NN * HID, HID, HID, HID / 8,
                                         W2, root2, b2, Y2);
    // 7) layer 2 edge aggregation into h2
    edge_scatter_kernel<<<(NE * 32 + TB - 1) / TB, TB>>>(ei, et, Y2, Y2 + (size_t)3 * NN * HID);
    // 8) pool (relu fused on read)
    pool_kernel<<<(NN * 32 + TB - 1) / TB, TB>>>(batch, Y2 + (size_t)3 * NN * HID);
    // 9) classifier head
    final_kernel<<<(GG + TB - 1) / TB, TB>>>(lin_w, lin_b, out);
}

// round 3
// speedup vs baseline: 1.2680x; 1.2680x over previous
#include <cuda_runtime.h>
#include <cuda_bf16.h>
#include <cstdint>

// Problem constants
constexpr int NN   = 50000;   // nodes
constexpr int NE   = 640000;  // edges
constexpr int RR   = 3;       // relations
constexpr int HID  = 128;
constexpr int GG   = 512;     // graphs
constexpr int K1   = 129;     // layer-1 K
constexpr int KP1  = 144;     // padded (multiple of 16)
constexpr int K2   = 128;
constexpr int KP2  = 128;

// ---------------- scratch (static device globals) -----------------------------------
__device__ __nv_bfloat16 g_A1h[(size_t)NN * KP1];
__device__ __nv_bfloat16 g_A1l[(size_t)NN * KP1];
__device__ __nv_bfloat16 g_A2h[(size_t)NN * KP2];
__device__ __nv_bfloat16 g_A2l[(size_t)NN * KP2];
__device__ __nv_bfloat16 g_B1h[512 * KP1];
__device__ __nv_bfloat16 g_B1l[512 * KP1];
__device__ __nv_bfloat16 g_B2h[512 * KP2];
__device__ __nv_bfloat16 g_B2l[512 * KP2];
__device__ float g_Y1[(size_t)4 * NN * HID];       // y0|y1|y2|h1 sections
__device__ float g_Y2[(size_t)4 * NN * HID];       // y0|y1|y2|h2 sections
__device__ int   g_cnt[RR * NN];
__device__ float g_inv[RR * NN];
__device__ float g_pool[GG * HID];
__device__ int   g_gcnt[GG];

// ---------------- small kernels ------------------------------------------------------

__global__ void zero_misc_kernel() {
    int i = blockIdx.x * blockDim.x + threadIdx.x;
    if (i < RR * NN) g_cnt[i] = 0;
    if (i < GG * HID) g_pool[i] = 0.f;
    if (i < GG) g_gcnt[i] = 0;
}

__global__ void count_edges_kernel(const int* __restrict__ ei, const int* __restrict__ et) {
    int e = blockIdx.x * blockDim.x + threadIdx.x;
    if (e >= NE) return;
    atomicAdd(&g_cnt[et[e] * NN + ei[NE + e]], 1);
}

__global__ void make_inv_kernel() {
    int i = blockIdx.x * blockDim.x + threadIdx.x;
    if (i >= RR * NN) return;
    int c = g_cnt[i];
    g_inv[i] = 1.f / (float)(c > 0 ? c : 1);
}

__device__ __forceinline__ void split_store(float v, __nv_bfloat16* ph, __nv_bfloat16* pl) {
    __nv_bfloat16 h = __float2bfloat16(v);
    *ph = h;
    *pl = __float2bfloat16(v - __bfloat162float(h));
}

__global__ void build_x1_kernel(const float* __restrict__ pos,
                                const int* __restrict__ sid,
                                const int* __restrict__ cid,
                                const float* __restrict__ se,
                                const float* __restrict__ ce) {
    int idx = blockIdx.x * blockDim.x + threadIdx.x;
    if (idx >= NN * KP1) return;
    int n = idx / KP1;
    int j = idx - n * KP1;
    float v;
    if (j < 64)       v = se[sid[n] * 64 + j];
    else if (j < 128) v = ce[cid[n] * 64 + (j - 64)];
    else if (j == 128) v = pos[n];
    else               v = 0.f;
    split_store(v, &g_A1h[idx], &g_A1l[idx]);
}

// Convert [W_r | root] (f32, [K][128] per section) to n-major bf16 hi/lo [512][Kp]
__global__ void conv_B_kernel(const float* __restrict__ W, const float* __restrict__ root,
                              int K, int Kp,
                              __nv_bfloat16* __restrict__ Bh, __nv_bfloat16* __restrict__ Bl) {
    int idx = blockIdx.x * blockDim.x + threadIdx.x;
    if (idx >= 512 * Kp) return;
    int nc = idx / Kp;
    int k  = idx - nc * Kp;
    int s  = nc >> 7;
    int n  = nc & 127;
    float v = 0.f;
    if (k < K) v = (s < 3) ? W[((size_t)s * K + k) * 128 + n] : root[(size_t)k * 128 + n];
    split_store(v, &Bh[idx], &Bl[idx]);
}

// relu(h1) -> bf16 hi/lo A for layer 2
__global__ void relu_conv_kernel(const float* __restrict__ h) {
    int idx = blockIdx.x * blockDim.x + threadIdx.x;
    if (idx >= NN * HID) return;
    float v = fmaxf(h[idx], 0.f);
    split_store(v, &g_A2h[idx], &g_A2l[idx]);
}

// ---------------- tensor-core GEMM --------------------------------------------------
// C[N, 4*128] = A @ [W0|W1|W2|root] with bf16 hi/lo split (3 MMAs).
// BM=128, BN=64 (grid.y = section*2 + half), 256 threads (8 warps: 4m x 2n),
// cp.async double-buffered k-chunks of 16.

__device__ __forceinline__ void cp16(uint32_t dst, const void* src) {
    asm volatile("cp.async.cg.shared.global [%0], [%1], 16;" :: "r"(dst), "l"(src));
}

__device__ __forceinline__ void mma_bf16(float* c, const uint32_t* a, uint32_t b0, uint32_t b1) {
    asm volatile(
        "mma.sync.aligned.m16n8k16.row.col.f32.bf16.bf16.f32 "
        "{%0,%1,%2,%3}, {%4,%5,%6,%7}, {%8,%9}, {%0,%1,%2,%3};"
        : "+f"(c[0]), "+f"(c[1]), "+f"(c[2]), "+f"(c[3])
        : "r"(a[0]), "r"(a[1]), "r"(a[2]), "r"(a[3]), "r"(b0), "r"(b1));
}

__global__ void __launch_bounds__(256, 2) gemm_tc_kernel(
    const __nv_bfloat16* __restrict__ Ah, const __nv_bfloat16* __restrict__ Al,
    int Kp, int KT,
    const __nv_bfloat16* __restrict__ Bh, const __nv_bfloat16* __restrict__ Bl,
    const float* __restrict__ bias, float* __restrict__ Y)
{
    // smem rows padded to 24 elems (48B) for conflict-free ldmatrix / LDS
    __shared__ __align__(16) __nv_bfloat16 sA[2][2][128][24];  // [buf][split][row][k]
    __shared__ __align__(16) __nv_bfloat16 sB[2][2][64][24];   // [buf][split][n][k]

    const int tid  = threadIdx.x;
    const int wid  = tid >> 5;
    const int lane = tid & 31;
    const int wm   = wid & 3;     // 0..3 : 32 rows each
    const int wn   = wid >> 2;    // 0..1 : 32 cols each
    const int m0   = blockIdx.x * 128;
    const int sec  = blockIdx.y >> 1;
    const int nh   = blockIdx.y & 1;
    const int nrow0 = sec * 128 + nh * 64;   // row base into Bt [512][Kp]

    const uint32_t sA_u32 = (uint32_t)__cvta_generic_to_shared(&sA[0][0][0][0]);
    const uint32_t sB_u32 = (uint32_t)__cvta_generic_to_shared(&sB[0][0][0][0]);

    float c[2][4][4] = {};

    // chunk loader: 512 A segs (16B) + 256 B segs; 3 cp.async per thread
    auto load_chunk = [&](int ks, int buf) {
        const int k0 = ks * 16;
        #pragma unroll
        for (int rep = 0; rep < 2; rep++) {
            int s = tid + rep * 256;
            int split = s >> 8;
            int rr    = (s & 255) >> 1;
            int half  = s & 1;
            if (m0 + rr < NN) {
                const __nv_bfloat16* src =
                    (split ? Al : Ah) + (size_t)(m0 + rr) * Kp + k0 + half * 8;
                uint32_t dst = sA_u32 +
                    ((((buf * 2 + split) * 128 + rr) * 24 + half * 8) << 1);
                cp16(dst, src);
            }
        }
        {
            int split = tid >> 7;
            int rr    = (tid & 127) >> 1;
            int half  = tid & 1;
            const __nv_bfloat16* src =
                (split ? Bl : Bh) + (size_t)(nrow0 + rr) * Kp + k0 + half * 8;
            uint32_t dst = sB_u32 +
                ((((buf * 2 + split) * 64 + rr) * 24 + half * 8) << 1);
            cp16(dst, src);
        }
        asm volatile("cp.async.commit_group;" ::: "memory");
    };

    load_chunk(0, 0);

    for (int ks = 0; ks < KT; ks++) {
        const int buf = ks & 1;
        if (ks + 1 < KT) {
            load_chunk(ks + 1, buf ^ 1);
            asm volatile("cp.async.wait_group 1;" ::: "memory");
        } else {
            asm volatile("cp.async.wait_group 0;" ::: "memory");
        }
        __syncthreads();

        // A fragments (hi and lo) for both 16-row tiles
        uint32_t ah[2][4], al[2][4];
        #pragma unroll
        for (int mt = 0; mt < 2; mt++) {
            int row = wm * 32 + mt * 16 + (lane & 15);
            int cof = (lane >> 4) * 8;
            uint32_t addr_h = sA_u32 + ((((buf * 2 + 0) * 128 + row) * 24 + cof) << 1);
            uint32_t addr_l = sA_u32 + ((((buf * 2 + 1) * 128 + row) * 24 + cof) << 1);
            asm volatile("ldmatrix.sync.aligned.m8n8.x4.shared.b16 {%0,%1,%2,%3}, [%4];"
                         : "=r"(ah[mt][0]), "=r"(ah[mt][1]), "=r"(ah[mt][2]), "=r"(ah[mt][3])
                         : "r"(addr_h));
            asm volatile("ldmatrix.sync.aligned.m8n8.x4.shared.b16 {%0,%1,%2,%3}, [%4];"
                         : "=r"(al[mt][0]), "=r"(al[mt][1]), "=r"(al[mt][2]), "=r"(al[mt][3])
                         : "r"(addr_l));
        }

        #pragma unroll
        for (int nt = 0; nt < 4; nt++) {
            int nl = wn * 32 + nt * 8 + (lane >> 2);
            int kc = (lane & 3) * 2;
            const __nv_bfloat16* pbh = &sB[buf][0][nl][kc];
            const __nv_bfloat16* pbl = &sB[buf][1][nl][kc];
            uint32_t bh0 = *reinterpret_cast<const uint32_t*>(pbh);
            uint32_t bh1 = *reinterpret_cast<const uint32_t*>(pbh + 8);
            uint32_t bl0 = *reinterpret_cast<const uint32_t*>(pbl);
            uint32_t bl1 = *reinterpret_cast<const uint32_t*>(pbl + 8);
            #pragma unroll
            for (int mt = 0; mt < 2; mt++) {
                mma_bf16(c[mt][nt], ah[mt], bh0, bh1);   // hi*hi
                mma_bf16(c[mt][nt], ah[mt], bl0, bl1);   // hi*lo
                mma_bf16(c[mt][nt], al[mt], bh0, bh1);   // lo*hi
            }
        }
        __syncthreads();
    }

    // epilogue
    float* Csec = Y + (size_t)sec * NN * HID;
    #pragma unroll
    for (int mt = 0; mt < 2; mt++) {
        int row = m0 + wm * 32 + mt * 16 + (lane >> 2);
        #pragma unroll
        for (int nt = 0; nt < 4; nt++) {
            int col = nh * 64 + wn * 32 + nt * 8 + (lane & 3) * 2;
            float bx = 0.f, by = 0.f;
            if (sec == 3) { bx = bias[col]; by = bias[col + 1]; }
            if (row < NN) {
                float* p = Csec + (size_t)row * HID + col;
                p[0] = c[mt][nt][0] + bx;
                p[1] = c[mt][nt][1] + by;
            }
            if (row + 8 < NN) {
                float* p = Csec + (size_t)(row + 8) * HID + col;
                p[0] = c[mt][nt][2] + bx;
                p[1] = c[mt][nt][3] + by;
            }
        }
    }
}

// ---------------- edge scatter: warp per edge, vector f32 atomics --------------------
__global__ void edge_scatter_kernel(const int* __restrict__ ei,
                                    const int* __restrict__ et,
                                    const float* __restrict__ Ybase,
                                    float* __restrict__ out) {
    const int w = (blockIdx.x * blockDim.x + threadIdx.x) >> 5;
    if (w >= NE) return;
    const int lane = threadIdx.x & 31;
    const int src = ei[w];
    const int dst = ei[NE + w];
    const int r   = et[w];
    const float s = g_inv[r * NN + dst];
    float4 v = *reinterpret_cast<const float4*>(
        Ybase + ((size_t)r * NN + src) * HID + lane * 4);
    v.x *= s; v.y *= s; v.z *= s; v.w *= s;
    float* o = out + (size_t)dst * HID + lane * 4;
    asm volatile("red.global.add.v4.f32 [%0], {%1, %2, %3, %4};"
                 :: "l"(o), "f"(v.x), "f"(v.y), "f"(v.z), "f"(v.w) : "memory");
}

// ---------------- pooling: warp per node, relu fused on read -------------------------
__global__ void pool_kernel(const int* __restrict__ batch, const float* __restrict__ h2) {
    const int w = (blockIdx.x * blockDim.x + threadIdx.x) >> 5;
    if (w >= NN) return;
    const int lane = threadIdx.x & 31;
    const int g = batch[w];
    float4 v = *reinterpret_cast<const float4*>(h2 + (size_t)w * HID + lane * 4);
    v.x = fmaxf(v.x, 0.f); v.y = fmaxf(v.y, 0.f);
    v.z = fmaxf(v.z, 0.f); v.w = fmaxf(v.w, 0.f);
    float* o = g_pool + (size_t)g * HID + lane * 4;
    asm volatile("red.global.add.v4.f32 [%0], {%1, %2, %3, %4};"
                 :: "l"(o), "f"(v.x), "f"(v.y), "f"(v.z), "f"(v.w) : "memory");
    if (lane == 0) atomicAdd(&g_gcnt[g], 1);
}

__global__ void final_kernel(const float* __restrict__ lw, const float* __restrict__ lb,
                             float* __restrict__ out) {
    int g = blockIdx.x * blockDim.x + threadIdx.x;
    if (g >= GG) return;
    const int c = g_gcnt[g];
    const float inv = 1.f / (float)(c > 0 ? c : 1);
    float a0 = 0.f, a1 = 0.f, a2 = 0.f, a3 = 0.f;
    const float* p = g_pool + (size_t)g * HID;
    #pragma unroll 8
    for (int k = 0; k < HID; k++) {
        float v = p[k] * inv;
        a0 += v * lw[k * 4 + 0];
        a1 += v * lw[k * 4 + 1];
        a2 += v * lw[k * 4 + 2];
        a3 += v * lw[k * 4 + 3];
    }
    out[g * 4 + 0] = a0 + lb[0];
    out[g * 4 + 1] = a1 + lb[1];
    out[g * 4 + 2] = a2 + lb[2];
    out[g * 4 + 3] = a3 + lb[3];
}

// ---------------- launch --------------------------------------------------------------
extern "C" void kernel_launch(void* const* d_in, const int* in_sizes, int n_in,
                              void* d_out, int out_size) {
    const float* pos      = (const float*)d_in[0];
    const int*   shape_id = (const int*)  d_in[1];
    const int*   color_id = (const int*)  d_in[2];
    const int*   ei       = (const int*)  d_in[3];
    const int*   et       = (const int*)  d_in[4];
    const int*   batch    = (const int*)  d_in[5];
    const float* se       = (const float*)d_in[6];
    const float* ce       = (const float*)d_in[7];
    const float* W1       = (const float*)d_in[8];
    const float* root1    = (const float*)d_in[9];
    const float* b1       = (const float*)d_in[10];
    const float* W2       = (const float*)d_in[11];
    const float* root2    = (const float*)d_in[12];
    const float* b2       = (const float*)d_in[13];
    const float* lin_w    = (const float*)d_in[14];
    const float* lin_b    = (const float*)d_in[15];
    float* out = (float*)d_out;

    __nv_bfloat16 *A1h, *A1l, *A2h, *A2l, *B1h, *B1l, *B2h, *B2l;
    float *Y1, *Y2;
    cudaGetSymbolAddress((void**)&A1h, g_A1h);
    cudaGetSymbolAddress((void**)&A1l, g_A1l);
    cudaGetSymbolAddress((void**)&A2h, g_A2h);
    cudaGetSymbolAddress((void**)&A2l, g_A2l);
    cudaGetSymbolAddress((void**)&B1h, g_B1h);
    cudaGetSymbolAddress((void**)&B1l, g_B1l);
    cudaGetSymbolAddress((void**)&B2h, g_B2h);
    cudaGetSymbolAddress((void**)&B2l, g_B2l);
    cudaGetSymbolAddress((void**)&Y1, g_Y1);
    cudaGetSymbolAddress((void**)&Y2, g_Y2);

    const int TB = 256;

    zero_misc_kernel<<<(RR * NN + TB - 1) / TB, TB>>>();
    count_edges_kernel<<<(NE + TB - 1) / TB, TB>>>(ei, et);
    make_inv_kernel<<<(RR * NN + TB - 1) / TB, TB>>>();
    build_x1_kernel<<<(NN * KP1 + TB - 1) / TB, TB>>>(pos, shape_id, color_id, se, ce);
    conv_B_kernel<<<(512 * KP1 + TB - 1) / TB, TB>>>(W1, root1, K1, KP1, B1h, B1l);
    conv_B_kernel<<<(512 * KP2 + TB - 1) / TB, TB>>>(W2, root2, K2, KP2, B2h, B2l);

    dim3 gemm_grid((NN + 127) / 128, 8);
    // layer 1
    gemm_tc_kernel<<<gemm_grid, 256>>>(A1h, A1l, KP1, KP1 / 16, B1h, B1l, b1, Y1);
    edge_scatter_kernel<<<(NE * 32 + TB - 1) / TB, TB>>>(ei, et, Y1, Y1 + (size_t)3 * NN * HID);
    relu_conv_kernel<<<(NN * HID + TB - 1) / TB, TB>>>(Y1 + (size_t)3 * NN * HID);
    // layer 2
    gemm_tc_kernel<<<gemm_grid, 256>>>(A2h, A2l, KP2, KP2 / 16, B2h, B2l, b2, Y2);
    edge_scatter_kernel<<<(NE * 32 + TB - 1) / TB, TB>>>(ei, et, Y2, Y2 + (size_t)3 * NN * HID);
    // head
    pool_kernel<<<(NN * 32 + TB - 1) / TB, TB>>>(batch, Y2 + (size_t)3 * NN * HID);
    final_kernel<<<(GG + TB - 1) / TB, TB>>>(lin_w, lin_b, out);
}

// round 4
// speedup vs baseline: 1.5975x; 1.2599x over previous
#include <cuda_runtime.h>
#include <cuda_bf16.h>
#include <cstdint>

// Problem constants
constexpr int NN   = 50000;
constexpr int NE   = 640000;
constexpr int RR   = 3;
constexpr int HID  = 128;
constexpr int GG   = 512;
constexpr int K1   = 129;
constexpr int KP1  = 144;
constexpr int K2   = 128;
constexpr int KP2  = 128;
constexpr int SEG  = RR * NN;          // 150000 segments
constexpr int SCAN_T = 256;
constexpr int SCAN_V = 4;
constexpr int SCAN_E = SCAN_T * SCAN_V;            // 1024
constexpr int NBLK = (SEG + SCAN_E - 1) / SCAN_E;  // 147

// ---------------- scratch -------------------------------------------------------------
__device__ __nv_bfloat16 g_A1h[(size_t)NN * KP1];
__device__ __nv_bfloat16 g_A1l[(size_t)NN * KP1];
__device__ __nv_bfloat16 g_A2h[(size_t)NN * KP2];
__device__ __nv_bfloat16 g_A2l[(size_t)NN * KP2];
__device__ __nv_bfloat16 g_B1h[512 * KP1];
__device__ __nv_bfloat16 g_B1l[512 * KP1];
__device__ __nv_bfloat16 g_B2h[512 * KP2];
__device__ __nv_bfloat16 g_B2l[512 * KP2];
__device__ float g_Y1[(size_t)4 * NN * HID];   // y0|y1|y2|h1
__device__ float g_Y2[(size_t)4 * NN * HID];   // y0|y1|y2|h2
__device__ int   g_cnt[SEG];
__device__ float g_inv[SEG];
__device__ int   g_off[SEG];
__device__ int   g_cur[SEG];
__device__ int   g_bsum[NBLK];
__device__ int   g_csr[NE];
__device__ float g_pool[GG * HID];
__device__ int   g_gcnt[GG];

// ---------------- init / counting ------------------------------------------------------
__global__ void zero_misc_kernel() {
    int i = blockIdx.x * blockDim.x + threadIdx.x;
    if (i < SEG) g_cnt[i] = 0;
    if (i < GG * HID) g_pool[i] = 0.f;
    if (i < GG) g_gcnt[i] = 0;
}

__global__ void count_edges_kernel(const int* __restrict__ ei, const int* __restrict__ et) {
    int e = blockIdx.x * blockDim.x + threadIdx.x;
    if (e >= NE) return;
    atomicAdd(&g_cnt[et[e] * NN + ei[NE + e]], 1);
}

// ---------------- 3-kernel exclusive scan of g_cnt -> g_off ---------------------------
__global__ void scan1_kernel() {
    __shared__ int sh[SCAN_T];
    const int tid  = threadIdx.x;
    const int base = blockIdx.x * SCAN_E + tid * SCAN_V;
    int v[SCAN_V], s = 0;
    #pragma unroll
    for (int k = 0; k < SCAN_V; k++) {
        v[k] = (base + k < SEG) ? g_cnt[base + k] : 0;
        s += v[k];
    }
    sh[tid] = s;
    __syncthreads();
    for (int off = 1; off < SCAN_T; off <<= 1) {
        int t = (tid >= off) ? sh[tid - off] : 0;
        __syncthreads();
        sh[tid] += t;
        __syncthreads();
    }
    int run = sh[tid] - s;   // exclusive
    #pragma unroll
    for (int k = 0; k < SCAN_V; k++) {
        if (base + k < SEG) g_off[base + k] = run;
        run += v[k];
    }
    if (tid == SCAN_T - 1) g_bsum[blockIdx.x] = sh[tid];
}

__global__ void scan2_kernel() {
    __shared__ int sh[SCAN_T];
    const int tid = threadIdx.x;
    int v = (tid < NBLK) ? g_bsum[tid] : 0;
    sh[tid] = v;
    __syncthreads();
    for (int off = 1; off < SCAN_T; off <<= 1) {
        int t = (tid >= off) ? sh[tid - off] : 0;
        __syncthreads();
        sh[tid] += t;
        __syncthreads();
    }
    if (tid < NBLK) g_bsum[tid] = sh[tid] - v;
}

__global__ void scan3_kernel() {
    int i = blockIdx.x * blockDim.x + threadIdx.x;
    if (i >= SEG) return;
    int o = g_off[i] + g_bsum[i / SCAN_E];
    g_off[i] = o;
    g_cur[i] = o;
    int c = g_cnt[i];
    g_inv[i] = 1.f / (float)(c > 0 ? c : 1);
}

__global__ void fill_csr_kernel(const int* __restrict__ ei, const int* __restrict__ et) {
    int e = blockIdx.x * blockDim.x + threadIdx.x;
    if (e >= NE) return;
    int seg = et[e] * NN + ei[NE + e];
    int pos = atomicAdd(&g_cur[seg], 1);
    g_csr[pos] = ei[e];
}

// ---------------- feature build --------------------------------------------------------
struct __align__(8) bh4 { __nv_bfloat16 v[4]; };

__device__ __forceinline__ void split4_store(float4 v, __nv_bfloat16* ph, __nv_bfloat16* pl) {
    bh4 h, l;
    float a[4] = {v.x, v.y, v.z, v.w};
    #pragma unroll
    for (int k = 0; k < 4; k++) {
        __nv_bfloat16 hb = __float2bfloat16(a[k]);
        h.v[k] = hb;
        l.v[k] = __float2bfloat16(a[k] - __bfloat162float(hb));
    }
    *reinterpret_cast<bh4*>(ph) = h;
    *reinterpret_cast<bh4*>(pl) = l;
}

__global__ void build_x1_kernel(const float* __restrict__ pos,
                                const int* __restrict__ sid,
                                const int* __restrict__ cid,
                                const float* __restrict__ se,
                                const float* __restrict__ ce) {
    constexpr int QW = KP1 / 4;   // 36 quads per node
    int idx = blockIdx.x * blockDim.x + threadIdx.x;
    if (idx >= NN * QW) return;
    int n = idx / QW;
    int j = (idx - n * QW) * 4;
    float4 v;
    if (j < 64)        v = *reinterpret_cast<const float4*>(se + sid[n] * 64 + j);
    else if (j < 128)  v = *reinterpret_cast<const float4*>(ce + cid[n] * 64 + (j - 64));
    else if (j == 128) v = make_float4(pos[n], 0.f, 0.f, 0.f);
    else               v = make_float4(0.f, 0.f, 0.f, 0.f);
    size_t o = (size_t)n * KP1 + j;
    split4_store(v, &g_A1h[o], &g_A1l[o]);
}

__global__ void conv_B_kernel(const float* __restrict__ W, const float* __restrict__ root,
                              int K, int Kp,
                              __nv_bfloat16* __restrict__ Bh, __nv_bfloat16* __restrict__ Bl) {
    int idx = blockIdx.x * blockDim.x + threadIdx.x;
    if (idx >= 512 * Kp) return;
    int nc = idx / Kp;
    int k  = idx - nc * Kp;
    int s  = nc >> 7;
    int n  = nc & 127;
    float v = 0.f;
    if (k < K) v = (s < 3) ? W[((size_t)s * K + k) * 128 + n] : root[(size_t)k * 128 + n];
    __nv_bfloat16 h = __float2bfloat16(v);
    Bh[idx] = h;
    Bl[idx] = __float2bfloat16(v - __bfloat162float(h));
}

// ---------------- tensor-core GEMM (unchanged from R2) --------------------------------
__device__ __forceinline__ void cp16(uint32_t dst, const void* src) {
    asm volatile("cp.async.cg.shared.global [%0], [%1], 16;" :: "r"(dst), "l"(src));
}

__device__ __forceinline__ void mma_bf16(float* c, const uint32_t* a, uint32_t b0, uint32_t b1) {
    asm volatile(
        "mma.sync.aligned.m16n8k16.row.col.f32.bf16.bf16.f32 "
        "{%0,%1,%2,%3}, {%4,%5,%6,%7}, {%8,%9}, {%0,%1,%2,%3};"
        : "+f"(c[0]), "+f"(c[1]), "+f"(c[2]), "+f"(c[3])
        : "r"(a[0]), "r"(a[1]), "r"(a[2]), "r"(a[3]), "r"(b0), "r"(b1));
}

__global__ void __launch_bounds__(256, 2) gemm_tc_kernel(
    const __nv_bfloat16* __restrict__ Ah, const __nv_bfloat16* __restrict__ Al,
    int Kp, int KT,
    const __nv_bfloat16* __restrict__ Bh, const __nv_bfloat16* __restrict__ Bl,
    const float* __restrict__ bias, float* __restrict__ Y)
{
    __shared__ __align__(16) __nv_bfloat16 sA[2][2][128][24];
    __shared__ __align__(16) __nv_bfloat16 sB[2][2][64][24];

    const int tid  = threadIdx.x;
    const int wid  = tid >> 5;
    const int lane = tid & 31;
    const int wm   = wid & 3;
    const int wn   = wid >> 2;
    const int m0   = blockIdx.x * 128;
    const int sec  = blockIdx.y >> 1;
    const int nh   = blockIdx.y & 1;
    const int nrow0 = sec * 128 + nh * 64;

    const uint32_t sA_u32 = (uint32_t)__cvta_generic_to_shared(&sA[0][0][0][0]);
    const uint32_t sB_u32 = (uint32_t)__cvta_generic_to_shared(&sB[0][0][0][0]);

    float c[2][4][4] = {};

    auto load_chunk = [&](int ks, int buf) {
        const int k0 = ks * 16;
        #pragma unroll
        for (int rep = 0; rep < 2; rep++) {
            int s = tid + rep * 256;
            int split = s >> 8;
            int rr    = (s & 255) >> 1;
            int half  = s & 1;
            if (m0 + rr < NN) {
                const __nv_bfloat16* src =
                    (split ? Al : Ah) + (size_t)(m0 + rr) * Kp + k0 + half * 8;
                uint32_t dst = sA_u32 + ((((buf * 2 + split) * 128 + rr) * 24 + half * 8) << 1);
                cp16(dst, src);
            }
        }
        {
            int split = tid >> 7;
            int rr    = (tid & 127) >> 1;
            int half  = tid & 1;
            const __nv_bfloat16* src =
                (split ? Bl : Bh) + (size_t)(nrow0 + rr) * Kp + k0 + half * 8;
            uint32_t dst = sB_u32 + ((((buf * 2 + split) * 64 + rr) * 24 + half * 8) << 1);
            cp16(dst, src);
        }
        asm volatile("cp.async.commit_group;" ::: "memory");
    };

    load_chunk(0, 0);

    for (int ks = 0; ks < KT; ks++) {
        const int buf = ks & 1;
        if (ks + 1 < KT) {
            load_chunk(ks + 1, buf ^ 1);
            asm volatile("cp.async.wait_group 1;" ::: "memory");
        } else {
            asm volatile("cp.async.wait_group 0;" ::: "memory");
        }
        __syncthreads();

        uint32_t ah[2][4], al[2][4];
        #pragma unroll
        for (int mt = 0; mt < 2; mt++) {
            int row = wm * 32 + mt * 16 + (lane & 15);
            int cof = (lane >> 4) * 8;
            uint32_t addr_h = sA_u32 + ((((buf * 2 + 0) * 128 + row) * 24 + cof) << 1);
            uint32_t addr_l = sA_u32 + ((((buf * 2 + 1) * 128 + row) * 24 + cof) << 1);
            asm volatile("ldmatrix.sync.aligned.m8n8.x4.shared.b16 {%0,%1,%2,%3}, [%4];"
                         : "=r"(ah[mt][0]), "=r"(ah[mt][1]), "=r"(ah[mt][2]), "=r"(ah[mt][3])
                         : "r"(addr_h));
            asm volatile("ldmatrix.sync.aligned.m8n8.x4.shared.b16 {%0,%1,%2,%3}, [%4];"
                         : "=r"(al[mt][0]), "=r"(al[mt][1]), "=r"(al[mt][2]), "=r"(al[mt][3])
                         : "r"(addr_l));
        }

        #pragma unroll
        for (int nt = 0; nt < 4; nt++) {
            int nl = wn * 32 + nt * 8 + (lane >> 2);
            int kc = (lane & 3) * 2;
            const __nv_bfloat16* pbh = &sB[buf][0][nl][kc];
            const __nv_bfloat16* pbl = &sB[buf][1][nl][kc];
            uint32_t bh0 = *reinterpret_cast<const uint32_t*>(pbh);
            uint32_t bh1 = *reinterpret_cast<const uint32_t*>(pbh + 8);
            uint32_t bl0 = *reinterpret_cast<const uint32_t*>(pbl);
            uint32_t bl1 = *reinterpret_cast<const uint32_t*>(pbl + 8);
            #pragma unroll
            for (int mt = 0; mt < 2; mt++) {
                mma_bf16(c[mt][nt], ah[mt], bh0, bh1);
                mma_bf16(c[mt][nt], ah[mt], bl0, bl1);
                mma_bf16(c[mt][nt], al[mt], bh0, bh1);
            }
        }
        __syncthreads();
    }

    float* Csec = Y + (size_t)sec * NN * HID;
    #pragma unroll
    for (int mt = 0; mt < 2; mt++) {
        int row = m0 + wm * 32 + mt * 16 + (lane >> 2);
        #pragma unroll
        for (int nt = 0; nt < 4; nt++) {
            int col = nh * 64 + wn * 32 + nt * 8 + (lane & 3) * 2;
            float bx = 0.f, by = 0.f;
            if (sec == 3) { bx = bias[col]; by = bias[col + 1]; }
            if (row < NN) {
                float* p = Csec + (size_t)row * HID + col;
                p[0] = c[mt][nt][0] + bx;
                p[1] = c[mt][nt][1] + by;
            }
            if (row + 8 < NN) {
                float* p = Csec + (size_t)(row + 8) * HID + col;
                p[0] = c[mt][nt][2] + bx;
                p[1] = c[mt][nt][3] + by;
            }
        }
    }
}

// ---------------- CSR gather aggregation: warp per destination node -------------------
// LAYER==1: h = root-section + per-relation means; epilogue relu -> bf16 hi/lo A2.
// LAYER==2: same; epilogue relu -> red.add into g_pool[batch[n]] (pool fused).
template <int LAYER>
__global__ void aggregate_kernel(const int* __restrict__ batch,
                                 const float* __restrict__ Y) {
    const int w = (blockIdx.x * blockDim.x + threadIdx.x) >> 5;
    if (w >= NN) return;
    const int lane = threadIdx.x & 31;

    float4 acc = *reinterpret_cast<const float4*>(
        Y + (size_t)3 * NN * HID + (size_t)w * HID + lane * 4);

    #pragma unroll
    for (int r = 0; r < RR; r++) {
        const int seg = r * NN + w;
        const int s0  = g_off[seg];
        const int c   = g_cnt[seg];
        const float sc = g_inv[seg];
        const float* Yr = Y + (size_t)r * NN * HID;
        float4 t = make_float4(0.f, 0.f, 0.f, 0.f);
        int nxt = (c > 0) ? g_csr[s0] : 0;
        for (int i = 0; i < c; i++) {
            int cur = nxt;
            if (i + 1 < c) nxt = g_csr[s0 + i + 1];
            float4 v = *reinterpret_cast<const float4*>(Yr + (size_t)cur * HID + lane * 4);
            t.x += v.x; t.y += v.y; t.z += v.z; t.w += v.w;
        }
        acc.x += t.x * sc; acc.y += t.y * sc; acc.z += t.z * sc; acc.w += t.w * sc;
    }

    acc.x = fmaxf(acc.x, 0.f); acc.y = fmaxf(acc.y, 0.f);
    acc.z = fmaxf(acc.z, 0.f); acc.w = fmaxf(acc.w, 0.f);

    if (LAYER == 1) {
        size_t o = (size_t)w * KP2 + lane * 4;
        split4_store(acc, &g_A2h[o], &g_A2l[o]);
    } else {
        const int g = batch[w];
        float* o = g_pool + (size_t)g * HID + lane * 4;
        asm volatile("red.global.add.v4.f32 [%0], {%1, %2, %3, %4};"
                     :: "l"(o), "f"(acc.x), "f"(acc.y), "f"(acc.z), "f"(acc.w) : "memory");
        if (lane == 0) atomicAdd(&g_gcnt[g], 1);
    }
}

__global__ void final_kernel(const float* __restrict__ lw, const float* __restrict__ lb,
                             float* __restrict__ out) {
    int g = blockIdx.x * blockDim.x + threadIdx.x;
    if (g >= GG) return;
    const int c = g_gcnt[g];
    const float inv = 1.f / (float)(c > 0 ? c : 1);
    float a0 = 0.f, a1 = 0.f, a2 = 0.f, a3 = 0.f;
    const float* p = g_pool + (size_t)g * HID;
    #pragma unroll 8
    for (int k = 0; k < HID; k++) {
        float v = p[k] * inv;
        a0 += v * lw[k * 4 + 0];
        a1 += v * lw[k * 4 + 1];
        a2 += v * lw[k * 4 + 2];
        a3 += v * lw[k * 4 + 3];
    }
    out[g * 4 + 0] = a0 + lb[0];
    out[g * 4 + 1] = a1 + lb[1];
    out[g * 4 + 2] = a2 + lb[2];
    out[g * 4 + 3] = a3 + lb[3];
}

// ---------------- launch ----------------------------------------------------------------
extern "C" void kernel_launch(void* const* d_in, const int* in_sizes, int n_in,
                              void* d_out, int out_size) {
    const float* pos      = (const float*)d_in[0];
    const int*   shape_id = (const int*)  d_in[1];
    const int*   color_id = (const int*)  d_in[2];
    const int*   ei       = (const int*)  d_in[3];
    const int*   et       = (const int*)  d_in[4];
    const int*   batch    = (const int*)  d_in[5];
    const float* se       = (const float*)d_in[6];
    const float* ce       = (const float*)d_in[7];
    const float* W1       = (const float*)d_in[8];
    const float* root1    = (const float*)d_in[9];
    const float* b1       = (const float*)d_in[10];
    const float* W2       = (const float*)d_in[11];
    const float* root2    = (const float*)d_in[12];
    const float* b2       = (const float*)d_in[13];
    const float* lin_w    = (const float*)d_in[14];
    const float* lin_b    = (const float*)d_in[15];
    float* out = (float*)d_out;

    __nv_bfloat16 *A1h, *A1l, *A2h, *A2l, *B1h, *B1l, *B2h, *B2l;
    float *Y1, *Y2;
    cudaGetSymbolAddress((void**)&A1h, g_A1h);
    cudaGetSymbolAddress((void**)&A1l, g_A1l);
    cudaGetSymbolAddress((void**)&A2h, g_A2h);
    cudaGetSymbolAddress((void**)&A2l, g_A2l);
    cudaGetSymbolAddress((void**)&B1h, g_B1h);
    cudaGetSymbolAddress((void**)&B1l, g_B1l);
    cudaGetSymbolAddress((void**)&B2h, g_B2h);
    cudaGetSymbolAddress((void**)&B2l, g_B2l);
    cudaGetSymbolAddress((void**)&Y1, g_Y1);
    cudaGetSymbolAddress((void**)&Y2, g_Y2);

    const int TB = 256;

    // init + counts
    zero_misc_kernel<<<(SEG + TB - 1) / TB, TB>>>();
    count_edges_kernel<<<(NE + TB - 1) / TB, TB>>>(ei, et);
    // CSR build
    scan1_kernel<<<NBLK, SCAN_T>>>();
    scan2_kernel<<<1, SCAN_T>>>();
    scan3_kernel<<<(SEG + TB - 1) / TB, TB>>>();
    fill_csr_kernel<<<(NE + TB - 1) / TB, TB>>>(ei, et);
    // features + weights
    build_x1_kernel<<<(NN * (KP1 / 4) + TB - 1) / TB, TB>>>(pos, shape_id, color_id, se, ce);
    conv_B_kernel<<<(512 * KP1 + TB - 1) / TB, TB>>>(W1, root1, K1, KP1, B1h, B1l);
    conv_B_kernel<<<(512 * KP2 + TB - 1) / TB, TB>>>(W2, root2, K2, KP2, B2h, B2l);

    dim3 gemm_grid((NN + 127) / 128, 8);
    // layer 1
    gemm_tc_kernel<<<gemm_grid, 256>>>(A1h, A1l, KP1, KP1 / 16, B1h, B1l, b1, Y1);
    aggregate_kernel<1><<<(NN * 32 + TB - 1) / TB, TB>>>(batch, Y1);
    // layer 2
    gemm_tc_kernel<<<gemm_grid, 256>>>(A2h, A2l, KP2, KP2 / 16, B2h, B2l, b2, Y2);
    aggregate_kernel<2><<<(NN * 32 + TB - 1) / TB, TB>>>(batch, Y2);
    // head
    final_kernel<<<(GG + TB - 1) / TB, TB>>>(lin_w, lin_b, out);
}

// round 5
// speedup vs baseline: 1.8274x; 1.1439x over previous
#include <cuda_runtime.h>
#include <cuda_bf16.h>
#include <cstdint>

// Problem constants
constexpr int NN   = 50000;
constexpr int NE   = 640000;
constexpr int RR   = 3;
constexpr int HID  = 128;
constexpr int GG   = 512;
constexpr int K1   = 129;
constexpr int KP1  = 144;
constexpr int K2   = 128;
constexpr int KP2  = 128;
constexpr int SEG  = RR * NN;
constexpr int SCAN_T = 256;
constexpr int SCAN_V = 4;
constexpr int SCAN_E = SCAN_T * SCAN_V;
constexpr int NBLK = (SEG + SCAN_E - 1) / SCAN_E;

// ---------------- scratch -------------------------------------------------------------
__device__ __nv_bfloat16 g_A1h[(size_t)NN * KP1];
__device__ __nv_bfloat16 g_A1l[(size_t)NN * KP1];
__device__ __nv_bfloat16 g_A2h[(size_t)NN * KP2];
__device__ __nv_bfloat16 g_A2l[(size_t)NN * KP2];
__device__ __nv_bfloat16 g_B1h[512 * KP1];
__device__ __nv_bfloat16 g_B1l[512 * KP1];
__device__ __nv_bfloat16 g_B2h[512 * KP2];
__device__ __nv_bfloat16 g_B2l[512 * KP2];
__device__ float g_Y1[(size_t)4 * NN * HID];   // y0|y1|y2|h1
__device__ float g_Y2[(size_t)4 * NN * HID];   // y0|y1|y2|h2
__device__ int   g_cnt[SEG];
__device__ float g_inv[SEG];
__device__ int   g_off[SEG];
__device__ int   g_cur[SEG];
__device__ int   g_bsum[NBLK];
__device__ int   g_csr[NE];
__device__ float g_pool[GG * HID];
__device__ int   g_gcnt[GG];

// ---------------- init / counting ------------------------------------------------------
__global__ void zero_misc_kernel() {
    int i = blockIdx.x * blockDim.x + threadIdx.x;
    if (i < SEG) g_cnt[i] = 0;
    if (i < GG * HID) g_pool[i] = 0.f;
    if (i < GG) g_gcnt[i] = 0;
}

__global__ void count_edges_kernel(const int* __restrict__ ei, const int* __restrict__ et) {
    int e = blockIdx.x * blockDim.x + threadIdx.x;
    if (e >= NE) return;
    atomicAdd(&g_cnt[et[e] * NN + ei[NE + e]], 1);
}

// ---------------- 3-kernel exclusive scan of g_cnt -> g_off ---------------------------
__global__ void scan1_kernel() {
    __shared__ int sh[SCAN_T];
    const int tid  = threadIdx.x;
    const int base = blockIdx.x * SCAN_E + tid * SCAN_V;
    int v[SCAN_V], s = 0;
    #pragma unroll
    for (int k = 0; k < SCAN_V; k++) {
        v[k] = (base + k < SEG) ? g_cnt[base + k] : 0;
        s += v[k];
    }
    sh[tid] = s;
    __syncthreads();
    for (int off = 1; off < SCAN_T; off <<= 1) {
        int t = (tid >= off) ? sh[tid - off] : 0;
        __syncthreads();
        sh[tid] += t;
        __syncthreads();
    }
    int run = sh[tid] - s;
    #pragma unroll
    for (int k = 0; k < SCAN_V; k++) {
        if (base + k < SEG) g_off[base + k] = run;
        run += v[k];
    }
    if (tid == SCAN_T - 1) g_bsum[blockIdx.x] = sh[tid];
}

__global__ void scan2_kernel() {
    __shared__ int sh[SCAN_T];
    const int tid = threadIdx.x;
    int v = (tid < NBLK) ? g_bsum[tid] : 0;
    sh[tid] = v;
    __syncthreads();
    for (int off = 1; off < SCAN_T; off <<= 1) {
        int t = (tid >= off) ? sh[tid - off] : 0;
        __syncthreads();
        sh[tid] += t;
        __syncthreads();
    }
    if (tid < NBLK) g_bsum[tid] = sh[tid] - v;
}

__global__ void scan3_kernel() {
    int i = blockIdx.x * blockDim.x + threadIdx.x;
    if (i >= SEG) return;
    int o = g_off[i] + g_bsum[i / SCAN_E];
    g_off[i] = o;
    g_cur[i] = o;
    int c = g_cnt[i];
    g_inv[i] = 1.f / (float)(c > 0 ? c : 1);
}

__global__ void fill_csr_kernel(const int* __restrict__ ei, const int* __restrict__ et) {
    int e = blockIdx.x * blockDim.x + threadIdx.x;
    if (e >= NE) return;
    int seg = et[e] * NN + ei[NE + e];
    int pos = atomicAdd(&g_cur[seg], 1);
    g_csr[pos] = ei[e];
}

// ---------------- feature build --------------------------------------------------------
struct __align__(8) bh4 { __nv_bfloat16 v[4]; };

__device__ __forceinline__ void split4_store(float4 v, __nv_bfloat16* ph, __nv_bfloat16* pl) {
    bh4 h, l;
    float a[4] = {v.x, v.y, v.z, v.w};
    #pragma unroll
    for (int k = 0; k < 4; k++) {
        __nv_bfloat16 hb = __float2bfloat16(a[k]);
        h.v[k] = hb;
        l.v[k] = __float2bfloat16(a[k] - __bfloat162float(hb));
    }
    *reinterpret_cast<bh4*>(ph) = h;
    *reinterpret_cast<bh4*>(pl) = l;
}

__global__ void build_x1_kernel(const float* __restrict__ pos,
                                const int* __restrict__ sid,
                                const int* __restrict__ cid,
                                const float* __restrict__ se,
                                const float* __restrict__ ce) {
    constexpr int QW = KP1 / 4;
    int idx = blockIdx.x * blockDim.x + threadIdx.x;
    if (idx >= NN * QW) return;
    int n = idx / QW;
    int j = (idx - n * QW) * 4;
    float4 v;
    if (j < 64)        v = *reinterpret_cast<const float4*>(se + sid[n] * 64 + j);
    else if (j < 128)  v = *reinterpret_cast<const float4*>(ce + cid[n] * 64 + (j - 64));
    else if (j == 128) v = make_float4(pos[n], 0.f, 0.f, 0.f);
    else               v = make_float4(0.f, 0.f, 0.f, 0.f);
    size_t o = (size_t)n * KP1 + j;
    split4_store(v, &g_A1h[o], &g_A1l[o]);
}

__global__ void conv_B_kernel(const float* __restrict__ W, const float* __restrict__ root,
                              int K, int Kp,
                              __nv_bfloat16* __restrict__ Bh, __nv_bfloat16* __restrict__ Bl) {
    int idx = blockIdx.x * blockDim.x + threadIdx.x;
    if (idx >= 512 * Kp) return;
    int nc = idx / Kp;
    int k  = idx - nc * Kp;
    int s  = nc >> 7;
    int n  = nc & 127;
    float v = 0.f;
    if (k < K) v = (s < 3) ? W[((size_t)s * K + k) * 128 + n] : root[(size_t)k * 128 + n];
    __nv_bfloat16 h = __float2bfloat16(v);
    Bh[idx] = h;
    Bl[idx] = __float2bfloat16(v - __bfloat162float(h));
}

// ---------------- tensor-core GEMM v2: BM=128, BN=128, grid.y=4 -----------------------
__device__ __forceinline__ void cp16(uint32_t dst, const void* src) {
    asm volatile("cp.async.cg.shared.global [%0], [%1], 16;" :: "r"(dst), "l"(src));
}

__device__ __forceinline__ void mma_bf16(float* c, const uint32_t* a, uint32_t b0, uint32_t b1) {
    asm volatile(
        "mma.sync.aligned.m16n8k16.row.col.f32.bf16.bf16.f32 "
        "{%0,%1,%2,%3}, {%4,%5,%6,%7}, {%8,%9}, {%0,%1,%2,%3};"
        : "+f"(c[0]), "+f"(c[1]), "+f"(c[2]), "+f"(c[3])
        : "r"(a[0]), "r"(a[1]), "r"(a[2]), "r"(a[3]), "r"(b0), "r"(b1));
}

__device__ __forceinline__ void ldmx4(uint32_t* r, uint32_t addr) {
    asm volatile("ldmatrix.sync.aligned.m8n8.x4.shared.b16 {%0,%1,%2,%3}, [%4];"
                 : "=r"(r[0]), "=r"(r[1]), "=r"(r[2]), "=r"(r[3]) : "r"(addr));
}

__global__ void __launch_bounds__(256, 2) gemm_tc_kernel(
    const __nv_bfloat16* __restrict__ Ah, const __nv_bfloat16* __restrict__ Al,
    int Kp, int KT,
    const __nv_bfloat16* __restrict__ Bh, const __nv_bfloat16* __restrict__ Bl,
    const float* __restrict__ bias, float* __restrict__ Y)
{
    __shared__ __align__(16) __nv_bfloat16 sA[2][2][128][24];
    __shared__ __align__(16) __nv_bfloat16 sB[2][2][128][24];

    const int tid  = threadIdx.x;
    const int wid  = tid >> 5;
    const int lane = tid & 31;
    const int wm   = wid & 3;     // 0..3 : 32 rows
    const int wn   = wid >> 2;    // 0..1 : 64 cols
    const int m0   = blockIdx.x * 128;
    const int sec  = blockIdx.y;  // 0..3
    const int nrow0 = sec * 128;

    const uint32_t sA_u32 = (uint32_t)__cvta_generic_to_shared(&sA[0][0][0][0]);
    const uint32_t sB_u32 = (uint32_t)__cvta_generic_to_shared(&sB[0][0][0][0]);

    float c[2][4][2][4] = {};   // [mt][ntp][ng][4]

    auto load_chunk = [&](int ks, int buf) {
        const int k0 = ks * 16;
        #pragma unroll
        for (int rep = 0; rep < 2; rep++) {
            int s = tid + rep * 256;
            int split = s >> 8;
            int rr    = (s & 255) >> 1;
            int half  = s & 1;
            if (m0 + rr < NN) {
                const __nv_bfloat16* src =
                    (split ? Al : Ah) + (size_t)(m0 + rr) * Kp + k0 + half * 8;
                uint32_t dst = sA_u32 + ((((buf * 2 + split) * 128 + rr) * 24 + half * 8) << 1);
                cp16(dst, src);
            }
        }
        #pragma unroll
        for (int rep = 0; rep < 2; rep++) {
            int s = tid + rep * 256;
            int split = s >> 8;
            int rr    = (s & 255) >> 1;
            int half  = s & 1;
            const __nv_bfloat16* src =
                (split ? Bl : Bh) + (size_t)(nrow0 + rr) * Kp + k0 + half * 8;
            uint32_t dst = sB_u32 + ((((buf * 2 + split) * 128 + rr) * 24 + half * 8) << 1);
            cp16(dst, src);
        }
        asm volatile("cp.async.commit_group;" ::: "memory");
    };

    load_chunk(0, 0);

    // B ldmatrix lane mapping: groups of 8 lanes -> (n offset, k offset) tiles
    const int bgrp = lane >> 3;
    const int brow = lane & 7;
    const int bn_off = (bgrp & 2) ? 8 : 0;
    const int bk_off = (bgrp & 1) * 8;

    for (int ks = 0; ks < KT; ks++) {
        const int buf = ks & 1;
        if (ks + 1 < KT) {
            load_chunk(ks + 1, buf ^ 1);
            asm volatile("cp.async.wait_group 1;" ::: "memory");
        } else {
            asm volatile("cp.async.wait_group 0;" ::: "memory");
        }
        __syncthreads();

        uint32_t ah[2][4], al[2][4];
        #pragma unroll
        for (int mt = 0; mt < 2; mt++) {
            int row = wm * 32 + mt * 16 + (lane & 15);
            int cof = (lane >> 4) * 8;
            ldmx4(ah[mt], sA_u32 + ((((buf * 2 + 0) * 128 + row) * 24 + cof) << 1));
            ldmx4(al[mt], sA_u32 + ((((buf * 2 + 1) * 128 + row) * 24 + cof) << 1));
        }

        #pragma unroll
        for (int ntp = 0; ntp < 4; ntp++) {
            const int n = wn * 64 + ntp * 16 + bn_off + brow;
            uint32_t bh[4], bl[4];
            ldmx4(bh, sB_u32 + ((((buf * 2 + 0) * 128 + n) * 24 + bk_off) << 1));
            ldmx4(bl, sB_u32 + ((((buf * 2 + 1) * 128 + n) * 24 + bk_off) << 1));
            #pragma unroll
            for (int mt = 0; mt < 2; mt++) {
                mma_bf16(c[mt][ntp][0], ah[mt], bh[0], bh[1]);
                mma_bf16(c[mt][ntp][0], ah[mt], bl[0], bl[1]);
                mma_bf16(c[mt][ntp][0], al[mt], bh[0], bh[1]);
                mma_bf16(c[mt][ntp][1], ah[mt], bh[2], bh[3]);
                mma_bf16(c[mt][ntp][1], ah[mt], bl[2], bl[3]);
                mma_bf16(c[mt][ntp][1], al[mt], bh[2], bh[3]);
            }
        }
        __syncthreads();
    }

    float* Csec = Y + (size_t)sec * NN * HID;
    #pragma unroll
    for (int mt = 0; mt < 2; mt++) {
        int row = m0 + wm * 32 + mt * 16 + (lane >> 2);
        #pragma unroll
        for (int ntp = 0; ntp < 4; ntp++) {
            #pragma unroll
            for (int ng = 0; ng < 2; ng++) {
                int col = wn * 64 + ntp * 16 + ng * 8 + (lane & 3) * 2;
                float bx = 0.f, by = 0.f;
                if (sec == 3) { bx = bias[col]; by = bias[col + 1]; }
                const float* cc = c[mt][ntp][ng];
                if (row < NN) {
                    float* p = Csec + (size_t)row * HID + col;
                    p[0] = cc[0] + bx;
                    p[1] = cc[1] + by;
                }
                if (row + 8 < NN) {
                    float* p = Csec + (size_t)(row + 8) * HID + col;
                    p[0] = cc[2] + bx;
                    p[1] = cc[3] + by;
                }
            }
        }
    }
}

// ---------------- CSR gather aggregation ----------------------------------------------
template <int LAYER>
__global__ void aggregate_kernel(const int* __restrict__ batch,
                                 const float* __restrict__ Y) {
    const int w = (blockIdx.x * blockDim.x + threadIdx.x) >> 5;
    if (w >= NN) return;
    const int lane = threadIdx.x & 31;

    float4 acc = *reinterpret_cast<const float4*>(
        Y + (size_t)3 * NN * HID + (size_t)w * HID + lane * 4);

    #pragma unroll
    for (int r = 0; r < RR; r++) {
        const int seg = r * NN + w;
        const int s0  = g_off[seg];
        const int c   = g_cnt[seg];
        const float sc = g_inv[seg];
        const float* Yr = Y + (size_t)r * NN * HID;
        float4 t = make_float4(0.f, 0.f, 0.f, 0.f);
        int nxt = (c > 0) ? g_csr[s0] : 0;
        for (int i = 0; i < c; i++) {
            int cur = nxt;
            if (i + 1 < c) nxt = g_csr[s0 + i + 1];
            float4 v = *reinterpret_cast<const float4*>(Yr + (size_t)cur * HID + lane * 4);
            t.x += v.x; t.y += v.y; t.z += v.z; t.w += v.w;
        }
        acc.x += t.x * sc; acc.y += t.y * sc; acc.z += t.z * sc; acc.w += t.w * sc;
    }

    acc.x = fmaxf(acc.x, 0.f); acc.y = fmaxf(acc.y, 0.f);
    acc.z = fmaxf(acc.z, 0.f); acc.w = fmaxf(acc.w, 0.f);

    if (LAYER == 1) {
        size_t o = (size_t)w * KP2 + lane * 4;
        split4_store(acc, &g_A2h[o], &g_A2l[o]);
    } else {
        const int g = batch[w];
        float* o = g_pool + (size_t)g * HID + lane * 4;
        asm volatile("red.global.add.v4.f32 [%0], {%1, %2, %3, %4};"
                     :: "l"(o), "f"(acc.x), "f"(acc.y), "f"(acc.z), "f"(acc.w) : "memory");
        if (lane == 0) atomicAdd(&g_gcnt[g], 1);
    }
}

__global__ void final_kernel(const float* __restrict__ lw, const float* __restrict__ lb,
                             float* __restrict__ out) {
    int g = blockIdx.x * blockDim.x + threadIdx.x;
    if (g >= GG) return;
    const int c = g_gcnt[g];
    const float inv = 1.f / (float)(c > 0 ? c : 1);
    float a0 = 0.f, a1 = 0.f, a2 = 0.f, a3 = 0.f;
    const float* p = g_pool + (size_t)g * HID;
    #pragma unroll 8
    for (int k = 0; k < HID; k++) {
        float v = p[k] * inv;
        a0 += v * lw[k * 4 + 0];
        a1 += v * lw[k * 4 + 1];
        a2 += v * lw[k * 4 + 2];
        a3 += v * lw[k * 4 + 3];
    }
    out[g * 4 + 0] = a0 + lb[0];
    out[g * 4 + 1] = a1 + lb[1];
    out[g * 4 + 2] = a2 + lb[2];
    out[g * 4 + 3] = a3 + lb[3];
}

// ---------------- launch ----------------------------------------------------------------
extern "C" void kernel_launch(void* const* d_in, const int* in_sizes, int n_in,
                              void* d_out, int out_size) {
    const float* pos      = (const float*)d_in[0];
    const int*   shape_id = (const int*)  d_in[1];
    const int*   color_id = (const int*)  d_in[2];
    const int*   ei       = (const int*)  d_in[3];
    const int*   et       = (const int*)  d_in[4];
    const int*   batch    = (const int*)  d_in[5];
    const float* se       = (const float*)d_in[6];
    const float* ce       = (const float*)d_in[7];
    const float* W1       = (const float*)d_in[8];
    const float* root1    = (const float*)d_in[9];
    const float* b1       = (const float*)d_in[10];
    const float* W2       = (const float*)d_in[11];
    const float* root2    = (const float*)d_in[12];
    const float* b2       = (const float*)d_in[13];
    const float* lin_w    = (const float*)d_in[14];
    const float* lin_b    = (const float*)d_in[15];
    float* out = (float*)d_out;

    __nv_bfloat16 *A1h, *A1l, *A2h, *A2l, *B1h, *B1l, *B2h, *B2l;
    float *Y1, *Y2;
    cudaGetSymbolAddress((void**)&A1h, g_A1h);
    cudaGetSymbolAddress((void**)&A1l, g_A1l);
    cudaGetSymbolAddress((void**)&A2h, g_A2h);
    cudaGetSymbolAddress((void**)&A2l, g_A2l);
    cudaGetSymbolAddress((void**)&B1h, g_B1h);
    cudaGetSymbolAddress((void**)&B1l, g_B1l);
    cudaGetSymbolAddress((void**)&B2h, g_B2h);
    cudaGetSymbolAddress((void**)&B2l, g_B2l);
    cudaGetSymbolAddress((void**)&Y1, g_Y1);
    cudaGetSymbolAddress((void**)&Y2, g_Y2);

    const int TB = 256;
    dim3 gemm_grid((NN + 127) / 128, 4);

    // Ordered so gemm layer-1 is launch index 3 (the one ncu profiles).
    build_x1_kernel<<<(NN * (KP1 / 4) + TB - 1) / TB, TB>>>(pos, shape_id, color_id, se, ce);
    conv_B_kernel<<<(512 * KP1 + TB - 1) / TB, TB>>>(W1, root1, K1, KP1, B1h, B1l);
    conv_B_kernel<<<(512 * KP2 + TB - 1) / TB, TB>>>(W2, root2, K2, KP2, B2h, B2l);
    gemm_tc_kernel<<<gemm_grid, 256>>>(A1h, A1l, KP1, KP1 / 16, B1h, B1l, b1, Y1);   // idx 3

    zero_misc_kernel<<<(SEG + TB - 1) / TB, TB>>>();
    count_edges_kernel<<<(NE + TB - 1) / TB, TB>>>(ei, et);
    scan1_kernel<<<NBLK, SCAN_T>>>();
    scan2_kernel<<<1, SCAN_T>>>();
    scan3_kernel<<<(SEG + TB - 1) / TB, TB>>>();
    fill_csr_kernel<<<(NE + TB - 1) / TB, TB>>>(ei, et);

    aggregate_kernel<1><<<(NN * 32 + TB - 1) / TB, TB>>>(batch, Y1);
    gemm_tc_kernel<<<gemm_grid, 256>>>(A2h, A2l, KP2, KP2 / 16, B2h, B2l, b2, Y2);
    aggregate_kernel<2><<<(NN * 32 + TB - 1) / TB, TB>>>(batch, Y2);
    final_kernel<<<(GG + TB - 1) / TB, TB>>>(lin_w, lin_b, out);
}

// round 6
// speedup vs baseline: 2.1578x; 1.1808x over previous
#include <cuda_runtime.h>
#include <cuda_bf16.h>
#include <cuda_fp16.h>
#include <cstdint>

// Problem constants
constexpr int NN   = 50000;
constexpr int NE   = 640000;
constexpr int RR   = 3;
constexpr int HID  = 128;
constexpr int GG   = 512;
constexpr int K1   = 129;
constexpr int KP1  = 144;
constexpr int K2   = 128;
constexpr int KP2  = 128;
constexpr int SEG  = RR * NN;
constexpr int SCAN_T = 256;
constexpr int SCAN_V = 4;
constexpr int SCAN_E = SCAN_T * SCAN_V;
constexpr int NBLK = (SEG + SCAN_E - 1) / SCAN_E;

constexpr int STAGES = 4;
constexpr int PLANE  = 128 * 24;                 // elems per split-plane
constexpr int STG_EL = 2 * PLANE;                // elems per stage (2 splits)
constexpr int B_BASE = STAGES * STG_EL;          // B offset in elems
constexpr int SMEM_BYTES = 2 * STAGES * STG_EL * 2;   // 96 KB

// ---------------- scratch -------------------------------------------------------------
__device__ __nv_bfloat16 g_A1h[(size_t)NN * KP1];
__device__ __nv_bfloat16 g_A1l[(size_t)NN * KP1];
__device__ __nv_bfloat16 g_A2h[(size_t)NN * KP2];
__device__ __nv_bfloat16 g_A2l[(size_t)NN * KP2];
__device__ __nv_bfloat16 g_B1h[512 * KP1];
__device__ __nv_bfloat16 g_B1l[512 * KP1];
__device__ __nv_bfloat16 g_B2h[512 * KP2];
__device__ __nv_bfloat16 g_B2l[512 * KP2];
__device__ __half g_Y1h[(size_t)3 * NN * HID];   // y0|y1|y2 (fp16)
__device__ __half g_Y2h[(size_t)3 * NN * HID];
__device__ float  g_H1[(size_t)NN * HID];        // root+bias section (fp32)
__device__ float  g_H2[(size_t)NN * HID];
__device__ int   g_cnt[SEG];
__device__ float g_inv[SEG];
__device__ int   g_off[SEG];
__device__ int   g_cur[SEG];
__device__ int   g_bsum[NBLK];
__device__ int   g_csr[NE];
__device__ float g_pool[GG * HID];
__device__ int   g_gcnt[GG];

// ---------------- init / counting ------------------------------------------------------
__global__ void zero_misc_kernel() {
    int i = blockIdx.x * blockDim.x + threadIdx.x;
    if (i < SEG) g_cnt[i] = 0;
    if (i < GG * HID) g_pool[i] = 0.f;
    if (i < GG) g_gcnt[i] = 0;
}

__global__ void count_edges_kernel(const int* __restrict__ ei, const int* __restrict__ et) {
    int e = blockIdx.x * blockDim.x + threadIdx.x;
    if (e >= NE) return;
    atomicAdd(&g_cnt[et[e] * NN + ei[NE + e]], 1);
}

// ---------------- 3-kernel exclusive scan ----------------------------------------------
__global__ void scan1_kernel() {
    __shared__ int sh[SCAN_T];
    const int tid  = threadIdx.x;
    const int base = blockIdx.x * SCAN_E + tid * SCAN_V;
    int v[SCAN_V], s = 0;
    #pragma unroll
    for (int k = 0; k < SCAN_V; k++) {
        v[k] = (base + k < SEG) ? g_cnt[base + k] : 0;
        s += v[k];
    }
    sh[tid] = s;
    __syncthreads();
    for (int off = 1; off < SCAN_T; off <<= 1) {
        int t = (tid >= off) ? sh[tid - off] : 0;
        __syncthreads();
        sh[tid] += t;
        __syncthreads();
    }
    int run = sh[tid] - s;
    #pragma unroll
    for (int k = 0; k < SCAN_V; k++) {
        if (base + k < SEG) g_off[base + k] = run;
        run += v[k];
    }
    if (tid == SCAN_T - 1) g_bsum[blockIdx.x] = sh[tid];
}

__global__ void scan2_kernel() {
    __shared__ int sh[SCAN_T];
    const int tid = threadIdx.x;
    int v = (tid < NBLK) ? g_bsum[tid] : 0;
    sh[tid] = v;
    __syncthreads();
    for (int off = 1; off < SCAN_T; off <<= 1) {
        int t = (tid >= off) ? sh[tid - off] : 0;
        __syncthreads();
        sh[tid] += t;
        __syncthreads();
    }
    if (tid < NBLK) g_bsum[tid] = sh[tid] - v;
}

__global__ void scan3_kernel() {
    int i = blockIdx.x * blockDim.x + threadIdx.x;
    if (i >= SEG) return;
    int o = g_off[i] + g_bsum[i / SCAN_E];
    g_off[i] = o;
    g_cur[i] = o;
    int c = g_cnt[i];
    g_inv[i] = 1.f / (float)(c > 0 ? c : 1);
}

__global__ void fill_csr_kernel(const int* __restrict__ ei, const int* __restrict__ et) {
    int e = blockIdx.x * blockDim.x + threadIdx.x;
    if (e >= NE) return;
    int seg = et[e] * NN + ei[NE + e];
    int pos = atomicAdd(&g_cur[seg], 1);
    g_csr[pos] = ei[e];
}

// ---------------- feature build --------------------------------------------------------
struct __align__(8) bh4 { __nv_bfloat16 v[4]; };

__device__ __forceinline__ void split4_store(float4 v, __nv_bfloat16* ph, __nv_bfloat16* pl) {
    bh4 h, l;
    float a[4] = {v.x, v.y, v.z, v.w};
    #pragma unroll
    for (int k = 0; k < 4; k++) {
        __nv_bfloat16 hb = __float2bfloat16(a[k]);
        h.v[k] = hb;
        l.v[k] = __float2bfloat16(a[k] - __bfloat162float(hb));
    }
    *reinterpret_cast<bh4*>(ph) = h;
    *reinterpret_cast<bh4*>(pl) = l;
}

__global__ void build_x1_kernel(const float* __restrict__ pos,
                                const int* __restrict__ sid,
                                const int* __restrict__ cid,
                                const float* __restrict__ se,
                                const float* __restrict__ ce) {
    constexpr int QW = KP1 / 4;
    int idx = blockIdx.x * blockDim.x + threadIdx.x;
    if (idx >= NN * QW) return;
    int n = idx / QW;
    int j = (idx - n * QW) * 4;
    float4 v;
    if (j < 64)        v = *reinterpret_cast<const float4*>(se + sid[n] * 64 + j);
    else if (j < 128)  v = *reinterpret_cast<const float4*>(ce + cid[n] * 64 + (j - 64));
    else if (j == 128) v = make_float4(pos[n], 0.f, 0.f, 0.f);
    else               v = make_float4(0.f, 0.f, 0.f, 0.f);
    size_t o = (size_t)n * KP1 + j;
    split4_store(v, &g_A1h[o], &g_A1l[o]);
}

__global__ void conv_B_kernel(const float* __restrict__ W, const float* __restrict__ root,
                              int K, int Kp,
                              __nv_bfloat16* __restrict__ Bh, __nv_bfloat16* __restrict__ Bl) {
    int idx = blockIdx.x * blockDim.x + threadIdx.x;
    if (idx >= 512 * Kp) return;
    int nc = idx / Kp;
    int k  = idx - nc * Kp;
    int s  = nc >> 7;
    int n  = nc & 127;
    float v = 0.f;
    if (k < K) v = (s < 3) ? W[((size_t)s * K + k) * 128 + n] : root[(size_t)k * 128 + n];
    __nv_bfloat16 h = __float2bfloat16(v);
    Bh[idx] = h;
    Bl[idx] = __float2bfloat16(v - __bfloat162float(h));
}

// ---------------- tensor-core GEMM v3: 4-stage multistage pipeline --------------------
__device__ __forceinline__ void cp16(uint32_t dst, const void* src) {
    asm volatile("cp.async.cg.shared.global [%0], [%1], 16;" :: "r"(dst), "l"(src));
}

__device__ __forceinline__ void mma_bf16(float* c, const uint32_t* a, uint32_t b0, uint32_t b1) {
    asm volatile(
        "mma.sync.aligned.m16n8k16.row.col.f32.bf16.bf16.f32 "
        "{%0,%1,%2,%3}, {%4,%5,%6,%7}, {%8,%9}, {%0,%1,%2,%3};"
        : "+f"(c[0]), "+f"(c[1]), "+f"(c[2]), "+f"(c[3])
        : "r"(a[0]), "r"(a[1]), "r"(a[2]), "r"(a[3]), "r"(b0), "r"(b1));
}

__device__ __forceinline__ void ldmx4(uint32_t* r, uint32_t addr) {
    asm volatile("ldmatrix.sync.aligned.m8n8.x4.shared.b16 {%0,%1,%2,%3}, [%4];"
                 : "=r"(r[0]), "=r"(r[1]), "=r"(r[2]), "=r"(r[3]) : "r"(addr));
}

__global__ void __launch_bounds__(256, 2) gemm_tc_kernel(
    const __nv_bfloat16* __restrict__ Ah, const __nv_bfloat16* __restrict__ Al,
    int Kp, int KT,
    const __nv_bfloat16* __restrict__ Bh, const __nv_bfloat16* __restrict__ Bl,
    const float* __restrict__ bias,
    __half* __restrict__ Yh,            // y sections [3, N, 128] fp16
    float* __restrict__ H)              // h section  [N, 128] fp32
{
    extern __shared__ __align__(16) __nv_bfloat16 smem[];

    const int tid  = threadIdx.x;
    const int wid  = tid >> 5;
    const int lane = tid & 31;
    const int wm   = wid & 3;
    const int wn   = wid >> 2;
    const int m0   = blockIdx.x * 128;
    const int sec  = blockIdx.y;
    const int nrow0 = sec * 128;

    const uint32_t s_u32 = (uint32_t)__cvta_generic_to_shared(smem);

    float c[2][4][2][4] = {};

    auto load_chunk = [&](int ks, int slot) {
        const int k0 = ks * 16;
        #pragma unroll
        for (int rep = 0; rep < 2; rep++) {
            int s = tid + rep * 256;
            int split = s >> 8;
            int rr    = (s & 255) >> 1;
            int half_ = s & 1;
            if (m0 + rr < NN) {
                const __nv_bfloat16* src =
                    (split ? Al : Ah) + (size_t)(m0 + rr) * Kp + k0 + half_ * 8;
                uint32_t dst = s_u32 +
                    ((slot * STG_EL + split * PLANE + rr * 24 + half_ * 8) << 1);
                cp16(dst, src);
            }
        }
        #pragma unroll
        for (int rep = 0; rep < 2; rep++) {
            int s = tid + rep * 256;
            int split = s >> 8;
            int rr    = (s & 255) >> 1;
            int half_ = s & 1;
            const __nv_bfloat16* src =
                (split ? Bl : Bh) + (size_t)(nrow0 + rr) * Kp + k0 + half_ * 8;
            uint32_t dst = s_u32 +
                ((B_BASE + slot * STG_EL + split * PLANE + rr * 24 + half_ * 8) << 1);
            cp16(dst, src);
        }
        asm volatile("cp.async.commit_group;" ::: "memory");
    };

    // prologue: stages 0..2
    #pragma unroll
    for (int s = 0; s < STAGES - 1; s++) load_chunk(s, s);

    const int bgrp = lane >> 3;
    const int brow = lane & 7;
    const int bn_off = (bgrp & 2) ? 8 : 0;
    const int bk_off = (bgrp & 1) * 8;

    for (int ks = 0; ks < KT; ks++) {
        asm volatile("cp.async.wait_group %0;" :: "n"(STAGES - 2) : "memory");
        __syncthreads();

        const int nk = ks + STAGES - 1;
        if (nk < KT) load_chunk(nk, nk % STAGES);
        else asm volatile("cp.async.commit_group;" ::: "memory");

        const int slot = ks % STAGES;
        const uint32_t a_base = s_u32 + ((slot * STG_EL) << 1);
        const uint32_t b_base = s_u32 + ((B_BASE + slot * STG_EL) << 1);

        uint32_t ah[2][4], al[2][4];
        #pragma unroll
        for (int mt = 0; mt < 2; mt++) {
            int row = wm * 32 + mt * 16 + (lane & 15);
            int cof = (lane >> 4) * 8;
            ldmx4(ah[mt], a_base + ((row * 24 + cof) << 1));
            ldmx4(al[mt], a_base + ((PLANE + row * 24 + cof) << 1));
        }

        #pragma unroll
        for (int ntp = 0; ntp < 4; ntp++) {
            const int n = wn * 64 + ntp * 16 + bn_off + brow;
            uint32_t bh[4], bl[4];
            ldmx4(bh, b_base + ((n * 24 + bk_off) << 1));
            ldmx4(bl, b_base + ((PLANE + n * 24 + bk_off) << 1));
            #pragma unroll
            for (int mt = 0; mt < 2; mt++) {
                mma_bf16(c[mt][ntp][0], ah[mt], bh[0], bh[1]);
                mma_bf16(c[mt][ntp][0], ah[mt], bl[0], bl[1]);
                mma_bf16(c[mt][ntp][0], al[mt], bh[0], bh[1]);
                mma_bf16(c[mt][ntp][1], ah[mt], bh[2], bh[3]);
                mma_bf16(c[mt][ntp][1], ah[mt], bl[2], bl[3]);
                mma_bf16(c[mt][ntp][1], al[mt], bh[2], bh[3]);
            }
        }
    }

    // epilogue: y sections -> fp16, h section -> fp32 (+bias)
    if (sec < 3) {
        __half* Ysec = Yh + (size_t)sec * NN * HID;
        #pragma unroll
        for (int mt = 0; mt < 2; mt++) {
            int row = m0 + wm * 32 + mt * 16 + (lane >> 2);
            #pragma unroll
            for (int ntp = 0; ntp < 4; ntp++) {
                #pragma unroll
                for (int ng = 0; ng < 2; ng++) {
                    int col = wn * 64 + ntp * 16 + ng * 8 + (lane & 3) * 2;
                    const float* cc = c[mt][ntp][ng];
                    if (row < NN)
                        *reinterpret_cast<__half2*>(Ysec + (size_t)row * HID + col) =
                            __floats2half2_rn(cc[0], cc[1]);
                    if (row + 8 < NN)
                        *reinterpret_cast<__half2*>(Ysec + (size_t)(row + 8) * HID + col) =
                            __floats2half2_rn(cc[2], cc[3]);
                }
            }
        }
    } else {
        #pragma unroll
        for (int mt = 0; mt < 2; mt++) {
            int row = m0 + wm * 32 + mt * 16 + (lane >> 2);
            #pragma unroll
            for (int ntp = 0; ntp < 4; ntp++) {
                #pragma unroll
                for (int ng = 0; ng < 2; ng++) {
                    int col = wn * 64 + ntp * 16 + ng * 8 + (lane & 3) * 2;
                    float bx = bias[col], by = bias[col + 1];
                    const float* cc = c[mt][ntp][ng];
                    if (row < NN) {
                        float* p = H + (size_t)row * HID + col;
                        p[0] = cc[0] + bx;
                        p[1] = cc[1] + by;
                    }
                    if (row + 8 < NN) {
                        float* p = H + (size_t)(row + 8) * HID + col;
                        p[0] = cc[2] + bx;
                        p[1] = cc[3] + by;
                    }
                }
            }
        }
    }
}

// ---------------- CSR gather aggregation (fp16 y) --------------------------------------
template <int LAYER>
__global__ void aggregate_kernel(const int* __restrict__ batch,
                                 const __half* __restrict__ Yh,
                                 const float* __restrict__ H) {
    const int w = (blockIdx.x * blockDim.x + threadIdx.x) >> 5;
    if (w >= NN) return;
    const int lane = threadIdx.x & 31;

    float4 acc = *reinterpret_cast<const float4*>(H + (size_t)w * HID + lane * 4);

    #pragma unroll
    for (int r = 0; r < RR; r++) {
        const int seg = r * NN + w;
        const int s0  = g_off[seg];
        const int c   = g_cnt[seg];
        const float sc = g_inv[seg];
        const __half* Yr = Yh + (size_t)r * NN * HID;
        float4 t = make_float4(0.f, 0.f, 0.f, 0.f);
        int nxt = (c > 0) ? g_csr[s0] : 0;
        for (int i = 0; i < c; i++) {
            int cur = nxt;
            if (i + 1 < c) nxt = g_csr[s0 + i + 1];
            uint2 raw = *reinterpret_cast<const uint2*>(
                Yr + (size_t)cur * HID + lane * 4);
            float2 a = __half22float2(*reinterpret_cast<const __half2*>(&raw.x));
            float2 b = __half22float2(*reinterpret_cast<const __half2*>(&raw.y));
            t.x += a.x; t.y += a.y; t.z += b.x; t.w += b.y;
        }
        acc.x += t.x * sc; acc.y += t.y * sc; acc.z += t.z * sc; acc.w += t.w * sc;
    }

    acc.x = fmaxf(acc.x, 0.f); acc.y = fmaxf(acc.y, 0.f);
    acc.z = fmaxf(acc.z, 0.f); acc.w = fmaxf(acc.w, 0.f);

    if (LAYER == 1) {
        size_t o = (size_t)w * KP2 + lane * 4;
        split4_store(acc, &g_A2h[o], &g_A2l[o]);
    } else {
        const int g = batch[w];
        float* o = g_pool + (size_t)g * HID + lane * 4;
        asm volatile("red.global.add.v4.f32 [%0], {%1, %2, %3, %4};"
                     :: "l"(o), "f"(acc.x), "f"(acc.y), "f"(acc.z), "f"(acc.w) : "memory");
        if (lane == 0) atomicAdd(&g_gcnt[g], 1);
    }
}

__global__ void final_kernel(const float* __restrict__ lw, const float* __restrict__ lb,
                             float* __restrict__ out) {
    int g = blockIdx.x * blockDim.x + threadIdx.x;
    if (g >= GG) return;
    const int c = g_gcnt[g];
    const float inv = 1.f / (float)(c > 0 ? c : 1);
    float a0 = 0.f, a1 = 0.f, a2 = 0.f, a3 = 0.f;
    const float* p = g_pool + (size_t)g * HID;
    #pragma unroll 8
    for (int k = 0; k < HID; k++) {
        float v = p[k] * inv;
        a0 += v * lw[k * 4 + 0];
        a1 += v * lw[k * 4 + 1];
        a2 += v * lw[k * 4 + 2];
        a3 += v * lw[k * 4 + 3];
    }
    out[g * 4 + 0] = a0 + lb[0];
    out[g * 4 + 1] = a1 + lb[1];
    out[g * 4 + 2] = a2 + lb[2];
    out[g * 4 + 3] = a3 + lb[3];
}

// ---------------- launch ----------------------------------------------------------------
extern "C" void kernel_launch(void* const* d_in, const int* in_sizes, int n_in,
                              void* d_out, int out_size) {
    const float* pos      = (const float*)d_in[0];
    const int*   shape_id = (const int*)  d_in[1];
    const int*   color_id = (const int*)  d_in[2];
    const int*   ei       = (const int*)  d_in[3];
    const int*   et       = (const int*)  d_in[4];
    const int*   batch    = (const int*)  d_in[5];
    const float* se       = (const float*)d_in[6];
    const float* ce       = (const float*)d_in[7];
    const float* W1       = (const float*)d_in[8];
    const float* root1    = (const float*)d_in[9];
    const float* b1       = (const float*)d_in[10];
    const float* W2       = (const float*)d_in[11];
    const float* root2    = (const float*)d_in[12];
    const float* b2       = (const float*)d_in[13];
    const float* lin_w    = (const float*)d_in[14];
    const float* lin_b    = (const float*)d_in[15];
    float* out = (float*)d_out;

    __nv_bfloat16 *A1h, *A1l, *A2h, *A2l, *B1h, *B1l, *B2h, *B2l;
    __half *Y1h, *Y2h;
    float *H1, *H2;
    cudaGetSymbolAddress((void**)&A1h, g_A1h);
    cudaGetSymbolAddress((void**)&A1l, g_A1l);
    cudaGetSymbolAddress((void**)&A2h, g_A2h);
    cudaGetSymbolAddress((void**)&A2l, g_A2l);
    cudaGetSymbolAddress((void**)&B1h, g_B1h);
    cudaGetSymbolAddress((void**)&B1l, g_B1l);
    cudaGetSymbolAddress((void**)&B2h, g_B2h);
    cudaGetSymbolAddress((void**)&B2l, g_B2l);
    cudaGetSymbolAddress((void**)&Y1h, g_Y1h);
    cudaGetSymbolAddress((void**)&Y2h, g_Y2h);
    cudaGetSymbolAddress((void**)&H1, g_H1);
    cudaGetSymbolAddress((void**)&H2, g_H2);

    static bool attr_set = false;
    if (!attr_set) {
        cudaFuncSetAttribute(gemm_tc_kernel,
                             cudaFuncAttributeMaxDynamicSharedMemorySize, SMEM_BYTES);
        attr_set = true;
    }

    const int TB = 256;
    dim3 gemm_grid((NN + 127) / 128, 4);

    // Ordered so gemm layer-1 is launch index 3 (the one ncu profiles).
    build_x1_kernel<<<(NN * (KP1 / 4) + TB - 1) / TB, TB>>>(pos, shape_id, color_id, se, ce);
    conv_B_kernel<<<(512 * KP1 + TB - 1) / TB, TB>>>(W1, root1, K1, KP1, B1h, B1l);
    conv_B_kernel<<<(512 * KP2 + TB - 1) / TB, TB>>>(W2, root2, K2, KP2, B2h, B2l);
    gemm_tc_kernel<<<gemm_grid, 256, SMEM_BYTES>>>(A1h, A1l, KP1, KP1 / 16,
                                                   B1h, B1l, b1, Y1h, H1);   // idx 3

    zero_misc_kernel<<<(SEG + TB - 1) / TB, TB>>>();
    count_edges_kernel<<<(NE + TB - 1) / TB, TB>>>(ei, et);
    scan1_kernel<<<NBLK, SCAN_T>>>();
    scan2_kernel<<<1, SCAN_T>>>();
    scan3_kernel<<<(SEG + TB - 1) / TB, TB>>>();
    fill_csr_kernel<<<(NE + TB - 1) / TB, TB>>>(ei, et);

    aggregate_kernel<1><<<(NN * 32 + TB - 1) / TB, TB>>>(batch, Y1h, H1);
    gemm_tc_kernel<<<gemm_grid, 256, SMEM_BYTES>>>(A2h, A2l, KP2, KP2 / 16,
                                                   B2h, B2l, b2, Y2h, H2);
    aggregate_kernel<2><<<(NN * 32 + TB - 1) / TB, TB>>>(batch, Y2h, H2);
    final_kernel<<<(GG + TB - 1) / TB, TB>>>(lin_w, lin_b, out);
}

// round 7
// speedup vs baseline: 2.4638x; 1.1418x over previous
#include <cuda_runtime.h>
#include <cuda_bf16.h>
#include <cuda_fp16.h>
#include <cstdint>

// Problem constants
constexpr int NN   = 50000;
constexpr int NE   = 640000;
constexpr int RR   = 3;
constexpr int HID  = 128;
constexpr int GG   = 512;
constexpr int K1   = 129;
constexpr int KP1  = 144;
constexpr int K2   = 128;
constexpr int KP2  = 128;
constexpr int SEG  = RR * NN;
constexpr int SCAN_T = 256;
constexpr int SCAN_V = 4;
constexpr int SCAN_E = SCAN_T * SCAN_V;
constexpr int NBLK = (SEG + SCAN_E - 1) / SCAN_E;

constexpr int STAGES = 4;
constexpr int PLANE  = 128 * 24;                  // elems per plane
constexpr int STG_EL = 3 * PLANE;                 // Ah | Al | B per stage
constexpr int SMEM_BYTES = STAGES * STG_EL * 2;   // 73728 B

// ---------------- scratch -------------------------------------------------------------
__device__ __half g_A1h[(size_t)NN * KP1];
__device__ __half g_A1l[(size_t)NN * KP1];
__device__ __half g_A2h[(size_t)NN * KP2];
__device__ __half g_A2l[(size_t)NN * KP2];
__device__ __half g_B1[512 * KP1];
__device__ __half g_B2[512 * KP2];
__device__ __half g_Y1h[(size_t)3 * NN * HID];   // y0|y1|y2 (fp16)
__device__ __half g_Y2h[(size_t)3 * NN * HID];
__device__ float  g_H1[(size_t)NN * HID];        // root+bias section (fp32)
__device__ float  g_H2[(size_t)NN * HID];
__device__ int   g_cnt[SEG];
__device__ float g_inv[SEG];
__device__ int   g_off[SEG];
__device__ int   g_cur[SEG];
__device__ int   g_bsum[NBLK];
__device__ int   g_csr[NE];
__device__ float g_pool[GG * HID];
__device__ int   g_gcnt[GG];

// ---------------- init / counting ------------------------------------------------------
__global__ void zero_misc_kernel() {
    int i = blockIdx.x * blockDim.x + threadIdx.x;
    if (i < SEG) g_cnt[i] = 0;
    if (i < GG * HID) g_pool[i] = 0.f;
    if (i < GG) g_gcnt[i] = 0;
}

__global__ void count_edges_kernel(const int* __restrict__ ei, const int* __restrict__ et) {
    int e = blockIdx.x * blockDim.x + threadIdx.x;
    if (e >= NE) return;
    atomicAdd(&g_cnt[et[e] * NN + ei[NE + e]], 1);
}

// ---------------- 3-kernel exclusive scan ----------------------------------------------
__global__ void scan1_kernel() {
    __shared__ int sh[SCAN_T];
    const int tid  = threadIdx.x;
    const int base = blockIdx.x * SCAN_E + tid * SCAN_V;
    int v[SCAN_V], s = 0;
    #pragma unroll
    for (int k = 0; k < SCAN_V; k++) {
        v[k] = (base + k < SEG) ? g_cnt[base + k] : 0;
        s += v[k];
    }
    sh[tid] = s;
    __syncthreads();
    for (int off = 1; off < SCAN_T; off <<= 1) {
        int t = (tid >= off) ? sh[tid - off] : 0;
        __syncthreads();
        sh[tid] += t;
        __syncthreads();
    }
    int run = sh[tid] - s;
    #pragma unroll
    for (int k = 0; k < SCAN_V; k++) {
        if (base + k < SEG) g_off[base + k] = run;
        run += v[k];
    }
    if (tid == SCAN_T - 1) g_bsum[blockIdx.x] = sh[tid];
}

__global__ void scan2_kernel() {
    __shared__ int sh[SCAN_T];
    const int tid = threadIdx.x;
    int v = (tid < NBLK) ? g_bsum[tid] : 0;
    sh[tid] = v;
    __syncthreads();
    for (int off = 1; off < SCAN_T; off <<= 1) {
        int t = (tid >= off) ? sh[tid - off] : 0;
        __syncthreads();
        sh[tid] += t;
        __syncthreads();
    }
    if (tid < NBLK) g_bsum[tid] = sh[tid] - v;
}

__global__ void scan3_kernel() {
    int i = blockIdx.x * blockDim.x + threadIdx.x;
    if (i >= SEG) return;
    int o = g_off[i] + g_bsum[i / SCAN_E];
    g_off[i] = o;
    g_cur[i] = o;
    int c = g_cnt[i];
    g_inv[i] = 1.f / (float)(c > 0 ? c : 1);
}

__global__ void fill_csr_kernel(const int* __restrict__ ei, const int* __restrict__ et) {
    int e = blockIdx.x * blockDim.x + threadIdx.x;
    if (e >= NE) return;
    int seg = et[e] * NN + ei[NE + e];
    int pos = atomicAdd(&g_cur[seg], 1);
    g_csr[pos] = ei[e];
}

// ---------------- feature build (fp16 hi/lo split) -------------------------------------
struct __align__(8) hf4 { __half v[4]; };

__device__ __forceinline__ void split4h_store(float4 v, __half* ph, __half* pl) {
    hf4 h, l;
    float a[4] = {v.x, v.y, v.z, v.w};
    #pragma unroll
    for (int k = 0; k < 4; k++) {
        __half hb = __float2half_rn(a[k]);
        h.v[k] = hb;
        l.v[k] = __float2half_rn(a[k] - __half2float(hb));
    }
    *reinterpret_cast<hf4*>(ph) = h;
    *reinterpret_cast<hf4*>(pl) = l;
}

__global__ void build_x1_kernel(const float* __restrict__ pos,
                                const int* __restrict__ sid,
                                const int* __restrict__ cid,
                                const float* __restrict__ se,
                                const float* __restrict__ ce) {
    constexpr int QW = KP1 / 4;
    int idx = blockIdx.x * blockDim.x + threadIdx.x;
    if (idx >= NN * QW) return;
    int n = idx / QW;
    int j = (idx - n * QW) * 4;
    float4 v;
    if (j < 64)        v = *reinterpret_cast<const float4*>(se + sid[n] * 64 + j);
    else if (j < 128)  v = *reinterpret_cast<const float4*>(ce + cid[n] * 64 + (j - 64));
    else if (j == 128) v = make_float4(pos[n], 0.f, 0.f, 0.f);
    else               v = make_float4(0.f, 0.f, 0.f, 0.f);
    size_t o = (size_t)n * KP1 + j;
    split4h_store(v, &g_A1h[o], &g_A1l[o]);
}

__global__ void conv_B_kernel(const float* __restrict__ W, const float* __restrict__ root,
                              int K, int Kp, __half* __restrict__ B) {
    int idx = blockIdx.x * blockDim.x + threadIdx.x;
    if (idx >= 512 * Kp) return;
    int nc = idx / Kp;
    int k  = idx - nc * Kp;
    int s  = nc >> 7;
    int n  = nc & 127;
    float v = 0.f;
    if (k < K) v = (s < 3) ? W[((size_t)s * K + k) * 128 + n] : root[(size_t)k * 128 + n];
    B[idx] = __float2half_rn(v);
}

// ---------------- tensor-core GEMM v4: fp16 2-pass, 4-stage pipeline ------------------
__device__ __forceinline__ void cp16(uint32_t dst, const void* src) {
    asm volatile("cp.async.cg.shared.global [%0], [%1], 16;" :: "r"(dst), "l"(src));
}

__device__ __forceinline__ void mma_f16(float* c, const uint32_t* a, uint32_t b0, uint32_t b1) {
    asm volatile(
        "mma.sync.aligned.m16n8k16.row.col.f32.f16.f16.f32 "
        "{%0,%1,%2,%3}, {%4,%5,%6,%7}, {%8,%9}, {%0,%1,%2,%3};"
        : "+f"(c[0]), "+f"(c[1]), "+f"(c[2]), "+f"(c[3])
        : "r"(a[0]), "r"(a[1]), "r"(a[2]), "r"(a[3]), "r"(b0), "r"(b1));
}

__device__ __forceinline__ void ldmx4(uint32_t* r, uint32_t addr) {
    asm volatile("ldmatrix.sync.aligned.m8n8.x4.shared.b16 {%0,%1,%2,%3}, [%4];"
                 : "=r"(r[0]), "=r"(r[1]), "=r"(r[2]), "=r"(r[3]) : "r"(addr));
}

__global__ void __launch_bounds__(256, 2) gemm_tc_kernel(
    const __half* __restrict__ Ah, const __half* __restrict__ Al,
    int Kp, int KT,
    const __half* __restrict__ B,
    const float* __restrict__ bias,
    __half* __restrict__ Yh,            // y sections [3, N, 128] fp16
    float* __restrict__ H)              // h section  [N, 128] fp32
{
    extern __shared__ __align__(16) __half smem[];

    const int tid  = threadIdx.x;
    const int wid  = tid >> 5;
    const int lane = tid & 31;
    const int wm   = wid & 3;
    const int wn   = wid >> 2;
    const int m0   = blockIdx.x * 128;
    const int sec  = blockIdx.y;
    const int nrow0 = sec * 128;

    const uint32_t s_u32 = (uint32_t)__cvta_generic_to_shared(smem);

    float c[2][4][2][4] = {};

    auto load_chunk = [&](int ks, int slot) {
        const int k0 = ks * 16;
        // A: 2 planes (hi, lo), 512 16B-chunks
        #pragma unroll
        for (int rep = 0; rep < 2; rep++) {
            int s = tid + rep * 256;
            int split = s >> 8;
            int rr    = (s & 255) >> 1;
            int half_ = s & 1;
            if (m0 + rr < NN) {
                const __half* src =
                    (split ? Al : Ah) + (size_t)(m0 + rr) * Kp + k0 + half_ * 8;
                uint32_t dst = s_u32 +
                    ((slot * STG_EL + split * PLANE + rr * 24 + half_ * 8) << 1);
                cp16(dst, src);
            }
        }
        // B: 1 plane, 256 chunks
        {
            int rr    = tid >> 1;
            int half_ = tid & 1;
            const __half* src = B + (size_t)(nrow0 + rr) * Kp + k0 + half_ * 8;
            uint32_t dst = s_u32 +
                ((slot * STG_EL + 2 * PLANE + rr * 24 + half_ * 8) << 1);
            cp16(dst, src);
        }
        asm volatile("cp.async.commit_group;" ::: "memory");
    };

    #pragma unroll
    for (int s = 0; s < STAGES - 1; s++) load_chunk(s, s);

    const int bgrp = lane >> 3;
    const int brow = lane & 7;
    const int bn_off = (bgrp & 2) ? 8 : 0;
    const int bk_off = (bgrp & 1) * 8;

    for (int ks = 0; ks < KT; ks++) {
        asm volatile("cp.async.wait_group %0;" :: "n"(STAGES - 2) : "memory");
        __syncthreads();

        const int nk = ks + STAGES - 1;
        if (nk < KT) load_chunk(nk, nk % STAGES);
        else asm volatile("cp.async.commit_group;" ::: "memory");

        const int slot = ks % STAGES;
        const uint32_t st_base = s_u32 + ((slot * STG_EL) << 1);

        uint32_t ah[2][4], al[2][4];
        #pragma unroll
        for (int mt = 0; mt < 2; mt++) {
            int row = wm * 32 + mt * 16 + (lane & 15);
            int cof = (lane >> 4) * 8;
            ldmx4(ah[mt], st_base + ((row * 24 + cof) << 1));
            ldmx4(al[mt], st_base + ((PLANE + row * 24 + cof) << 1));
        }

        #pragma unroll
        for (int ntp = 0; ntp < 4; ntp++) {
            const int n = wn * 64 + ntp * 16 + bn_off + brow;
            uint32_t bh[4];
            ldmx4(bh, st_base + ((2 * PLANE + n * 24 + bk_off) << 1));
            #pragma unroll
            for (int mt = 0; mt < 2; mt++) {
                mma_f16(c[mt][ntp][0], ah[mt], bh[0], bh[1]);
                mma_f16(c[mt][ntp][0], al[mt], bh[0], bh[1]);
                mma_f16(c[mt][ntp][1], ah[mt], bh[2], bh[3]);
                mma_f16(c[mt][ntp][1], al[mt], bh[2], bh[3]);
            }
        }
    }

    // epilogue
    if (sec < 3) {
        __half* Ysec = Yh + (size_t)sec * NN * HID;
        #pragma unroll
        for (int mt = 0; mt < 2; mt++) {
            int row = m0 + wm * 32 + mt * 16 + (lane >> 2);
            #pragma unroll
            for (int ntp = 0; ntp < 4; ntp++) {
                #pragma unroll
                for (int ng = 0; ng < 2; ng++) {
                    int col = wn * 64 + ntp * 16 + ng * 8 + (lane & 3) * 2;
                    const float* cc = c[mt][ntp][ng];
                    if (row < NN)
                        *reinterpret_cast<__half2*>(Ysec + (size_t)row * HID + col) =
                            __floats2half2_rn(cc[0], cc[1]);
                    if (row + 8 < NN)
                        *reinterpret_cast<__half2*>(Ysec + (size_t)(row + 8) * HID + col) =
                            __floats2half2_rn(cc[2], cc[3]);
                }
            }
        }
    } else {
        #pragma unroll
        for (int mt = 0; mt < 2; mt++) {
            int row = m0 + wm * 32 + mt * 16 + (lane >> 2);
            #pragma unroll
            for (int ntp = 0; ntp < 4; ntp++) {
                #pragma unroll
                for (int ng = 0; ng < 2; ng++) {
                    int col = wn * 64 + ntp * 16 + ng * 8 + (lane & 3) * 2;
                    float bx = bias[col], by = bias[col + 1];
                    const float* cc = c[mt][ntp][ng];
                    if (row < NN) {
                        float* p = H + (size_t)row * HID + col;
                        p[0] = cc[0] + bx;
                        p[1] = cc[1] + by;
                    }
                    if (row + 8 < NN) {
                        float* p = H + (size_t)(row + 8) * HID + col;
                        p[0] = cc[2] + bx;
                        p[1] = cc[3] + by;
                    }
                }
            }
        }
    }
}

// ---------------- CSR gather aggregation (fp16 y) --------------------------------------
template <int LAYER>
__global__ void aggregate_kernel(const int* __restrict__ batch,
                                 const __half* __restrict__ Yh,
                                 const float* __restrict__ H) {
    const int w = (blockIdx.x * blockDim.x + threadIdx.x) >> 5;
    if (w >= NN) return;
    const int lane = threadIdx.x & 31;

    float4 acc = *reinterpret_cast<const float4*>(H + (size_t)w * HID + lane * 4);

    #pragma unroll
    for (int r = 0; r < RR; r++) {
        const int seg = r * NN + w;
        const int s0  = g_off[seg];
        const int c   = g_cnt[seg];
        const float sc = g_inv[seg];
        const __half* Yr = Yh + (size_t)r * NN * HID;
        float4 t = make_float4(0.f, 0.f, 0.f, 0.f);
        int nxt = (c > 0) ? g_csr[s0] : 0;
        for (int i = 0; i < c; i++) {
            int cur = nxt;
            if (i + 1 < c) nxt = g_csr[s0 + i + 1];
            uint2 raw = *reinterpret_cast<const uint2*>(
                Yr + (size_t)cur * HID + lane * 4);
            float2 a = __half22float2(*reinterpret_cast<const __half2*>(&raw.x));
            float2 b = __half22float2(*reinterpret_cast<const __half2*>(&raw.y));
            t.x += a.x; t.y += a.y; t.z += b.x; t.w += b.y;
        }
        acc.x += t.x * sc; acc.y += t.y * sc; acc.z += t.z * sc; acc.w += t.w * sc;
    }

    acc.x = fmaxf(acc.x, 0.f); acc.y = fmaxf(acc.y, 0.f);
    acc.z = fmaxf(acc.z, 0.f); acc.w = fmaxf(acc.w, 0.f);

    if (LAYER == 1) {
        size_t o = (size_t)w * KP2 + lane * 4;
        split4h_store(acc, &g_A2h[o], &g_A2l[o]);
    } else {
        const int g = batch[w];
        float* o = g_pool + (size_t)g * HID + lane * 4;
        asm volatile("red.global.add.v4.f32 [%0], {%1, %2, %3, %4};"
                     :: "l"(o), "f"(acc.x), "f"(acc.y), "f"(acc.z), "f"(acc.w) : "memory");
        if (lane == 0) atomicAdd(&g_gcnt[g], 1);
    }
}

__global__ void final_kernel(const float* __restrict__ lw, const float* __restrict__ lb,
                             float* __restrict__ out) {
    int g = blockIdx.x * blockDim.x + threadIdx.x;
    if (g >= GG) return;
    const int c = g_gcnt[g];
    const float inv = 1.f / (float)(c > 0 ? c : 1);
    float a0 = 0.f, a1 = 0.f, a2 = 0.f, a3 = 0.f;
    const float* p = g_pool + (size_t)g * HID;
    #pragma unroll 8
    for (int k = 0; k < HID; k++) {
        float v = p[k] * inv;
        a0 += v * lw[k * 4 + 0];
        a1 += v * lw[k * 4 + 1];
        a2 += v * lw[k * 4 + 2];
        a3 += v * lw[k * 4 + 3];
    }
    out[g * 4 + 0] = a0 + lb[0];
    out[g * 4 + 1] = a1 + lb[1];
    out[g * 4 + 2] = a2 + lb[2];
    out[g * 4 + 3] = a3 + lb[3];
}

// ---------------- launch ----------------------------------------------------------------
extern "C" void kernel_launch(void* const* d_in, const int* in_sizes, int n_in,
                              void* d_out, int out_size) {
    const float* pos      = (const float*)d_in[0];
    const int*   shape_id = (const int*)  d_in[1];
    const int*   color_id = (const int*)  d_in[2];
    const int*   ei       = (const int*)  d_in[3];
    const int*   et       = (const int*)  d_in[4];
    const int*   batch    = (const int*)  d_in[5];
    const float* se       = (const float*)d_in[6];
    const float* ce       = (const float*)d_in[7];
    const float* W1       = (const float*)d_in[8];
    const float* root1    = (const float*)d_in[9];
    const float* b1       = (const float*)d_in[10];
    const float* W2       = (const float*)d_in[11];
    const float* root2    = (const float*)d_in[12];
    const float* b2       = (const float*)d_in[13];
    const float* lin_w    = (const float*)d_in[14];
    const float* lin_b    = (const float*)d_in[15];
    float* out = (float*)d_out;

    __half *A1h, *A1l, *A2h, *A2l, *B1, *B2, *Y1h, *Y2h;
    float *H1, *H2;
    cudaGetSymbolAddress((void**)&A1h, g_A1h);
    cudaGetSymbolAddress((void**)&A1l, g_A1l);
    cudaGetSymbolAddress((void**)&A2h, g_A2h);
    cudaGetSymbolAddress((void**)&A2l, g_A2l);
    cudaGetSymbolAddress((void**)&B1, g_B1);
    cudaGetSymbolAddress((void**)&B2, g_B2);
    cudaGetSymbolAddress((void**)&Y1h, g_Y1h);
    cudaGetSymbolAddress((void**)&Y2h, g_Y2h);
    cudaGetSymbolAddress((void**)&H1, g_H1);
    cudaGetSymbolAddress((void**)&H2, g_H2);

    static bool attr_set = false;
    if (!attr_set) {
        cudaFuncSetAttribute(gemm_tc_kernel,
                             cudaFuncAttributeMaxDynamicSharedMemorySize, SMEM_BYTES);
        attr_set = true;
    }

    const int TB = 256;
    dim3 gemm_grid((NN + 127) / 128, 4);

    // Ordered so gemm layer-1 is launch index 3 (the one ncu profiles).
    build_x1_kernel<<<(NN * (KP1 / 4) + TB - 1) / TB, TB>>>(pos, shape_id, color_id, se, ce);
    conv_B_kernel<<<(512 * KP1 + TB - 1) / TB, TB>>>(W1, root1, K1, KP1, B1);
    conv_B_kernel<<<(512 * KP2 + TB - 1) / TB, TB>>>(W2, root2, K2, KP2, B2);
    gemm_tc_kernel<<<gemm_grid, 256, SMEM_BYTES>>>(A1h, A1l, KP1, KP1 / 16,
                                                   B1, b1, Y1h, H1);   // idx 3

    zero_misc_kernel<<<(SEG + TB - 1) / TB, TB>>>();
    count_edges_kernel<<<(NE + TB - 1) / TB, TB>>>(ei, et);
    scan1_kernel<<<NBLK, SCAN_T>>>();
    scan2_kernel<<<1, SCAN_T>>>();
    scan3_kernel<<<(SEG + TB - 1) / TB, TB>>>();
    fill_csr_kernel<<<(NE + TB - 1) / TB, TB>>>(ei, et);

    aggregate_kernel<1><<<(NN * 32 + TB - 1) / TB, TB>>>(batch, Y1h, H1);
    gemm_tc_kernel<<<gemm_grid, 256, SMEM_BYTES>>>(A2h, A2l, KP2, KP2 / 16,
                                                   B2, b2, Y2h, H2);
    aggregate_kernel<2><<<(NN * 32 + TB - 1) / TB, TB>>>(batch, Y2h, H2);
    final_kernel<<<(GG + TB - 1) / TB, TB>>>(lin_w, lin_b, out);
}

// round 8
// speedup vs baseline: 2.9814x; 1.2101x over previous
#include <cuda_runtime.h>
#include <cuda_bf16.h>
#include <cuda_fp16.h>
#include <cstdint>

// Problem constants
constexpr int NN   = 50000;
constexpr int NE   = 640000;
constexpr int RR   = 3;
constexpr int HID  = 128;
constexpr int GG   = 512;
constexpr int K1   = 129;
constexpr int KP1  = 144;
constexpr int K2   = 128;
constexpr int KP2  = 128;
constexpr int SEG  = RR * NN;
constexpr int SCAN_T = 256;
constexpr int SCAN_V = 4;
constexpr int SCAN_E = SCAN_T * SCAN_V;
constexpr int NBLK = (SEG + SCAN_E - 1) / SCAN_E;

constexpr int STAGES = 4;
constexpr int PLANE  = 128 * 24;                  // elems per plane
constexpr int STG_EL = 2 * PLANE;                 // A | B per stage
constexpr int SMEM_BYTES = STAGES * STG_EL * 2;   // 49152 B

// ---------------- scratch -------------------------------------------------------------
__device__ __half g_A1[(size_t)NN * KP1];
__device__ __half g_A2[(size_t)NN * KP2];
__device__ __half g_B1[512 * KP1];
__device__ __half g_B2[512 * KP2];
__device__ __half g_Y1h[(size_t)3 * NN * HID];   // y0|y1|y2 (fp16)
__device__ __half g_Y2h[(size_t)3 * NN * HID];
__device__ float  g_H1[(size_t)NN * HID];        // root+bias section (fp32)
__device__ float  g_H2[(size_t)NN * HID];
__device__ int   g_cnt[SEG];
__device__ float g_inv[SEG];
__device__ int   g_off[SEG];
__device__ int   g_cur[SEG];
__device__ int   g_bsum[NBLK];
__device__ int   g_csr[NE];
__device__ float g_pool[GG * HID];
__device__ int   g_gcnt[GG];

// ---------------- init / counting ------------------------------------------------------
__global__ void zero_misc_kernel() {
    int i = blockIdx.x * blockDim.x + threadIdx.x;
    if (i < SEG) g_cnt[i] = 0;
    if (i < GG * HID) g_pool[i] = 0.f;
    if (i < GG) g_gcnt[i] = 0;
}

__global__ void count_edges_kernel(const int* __restrict__ ei, const int* __restrict__ et) {
    int e = blockIdx.x * blockDim.x + threadIdx.x;
    if (e >= NE) return;
    atomicAdd(&g_cnt[et[e] * NN + ei[NE + e]], 1);
}

// ---------------- 3-kernel exclusive scan ----------------------------------------------
__global__ void scan1_kernel() {
    __shared__ int sh[SCAN_T];
    const int tid  = threadIdx.x;
    const int base = blockIdx.x * SCAN_E + tid * SCAN_V;
    int v[SCAN_V], s = 0;
    #pragma unroll
    for (int k = 0; k < SCAN_V; k++) {
        v[k] = (base + k < SEG) ? g_cnt[base + k] : 0;
        s += v[k];
    }
    sh[tid] = s;
    __syncthreads();
    for (int off = 1; off < SCAN_T; off <<= 1) {
        int t = (tid >= off) ? sh[tid - off] : 0;
        __syncthreads();
        sh[tid] += t;
        __syncthreads();
    }
    int run = sh[tid] - s;
    #pragma unroll
    for (int k = 0; k < SCAN_V; k++) {
        if (base + k < SEG) g_off[base + k] = run;
        run += v[k];
    }
    if (tid == SCAN_T - 1) g_bsum[blockIdx.x] = sh[tid];
}

__global__ void scan2_kernel() {
    __shared__ int sh[SCAN_T];
    const int tid = threadIdx.x;
    int v = (tid < NBLK) ? g_bsum[tid] : 0;
    sh[tid] = v;
    __syncthreads();
    for (int off = 1; off < SCAN_T; off <<= 1) {
        int t = (tid >= off) ? sh[tid - off] : 0;
        __syncthreads();
        sh[tid] += t;
        __syncthreads();
    }
    if (tid < NBLK) g_bsum[tid] = sh[tid] - v;
}

__global__ void scan3_kernel() {
    int i = blockIdx.x * blockDim.x + threadIdx.x;
    if (i >= SEG) return;
    int o = g_off[i] + g_bsum[i / SCAN_E];
    g_off[i] = o;
    g_cur[i] = o;
    int c = g_cnt[i];
    g_inv[i] = 1.f / (float)(c > 0 ? c : 1);
}

__global__ void fill_csr_kernel(const int* __restrict__ ei, const int* __restrict__ et) {
    int e = blockIdx.x * blockDim.x + threadIdx.x;
    if (e >= NE) return;
    int seg = et[e] * NN + ei[NE + e];
    int pos = atomicAdd(&g_cur[seg], 1);
    g_csr[pos] = ei[e];
}

// ---------------- feature build (fp16) --------------------------------------------------
struct __align__(8) hf4 { __half v[4]; };

__device__ __forceinline__ void store4h(float4 v, __half* p) {
    hf4 h;
    h.v[0] = __float2half_rn(v.x);
    h.v[1] = __float2half_rn(v.y);
    h.v[2] = __float2half_rn(v.z);
    h.v[3] = __float2half_rn(v.w);
    *reinterpret_cast<hf4*>(p) = h;
}

__global__ void build_x1_kernel(const float* __restrict__ pos,
                                const int* __restrict__ sid,
                                const int* __restrict__ cid,
                                const float* __restrict__ se,
                                const float* __restrict__ ce) {
    constexpr int QW = KP1 / 4;
    int idx = blockIdx.x * blockDim.x + threadIdx.x;
    if (idx >= NN * QW) return;
    int n = idx / QW;
    int j = (idx - n * QW) * 4;
    float4 v;
    if (j < 64)        v = *reinterpret_cast<const float4*>(se + sid[n] * 64 + j);
    else if (j < 128)  v = *reinterpret_cast<const float4*>(ce + cid[n] * 64 + (j - 64));
    else if (j == 128) v = make_float4(pos[n], 0.f, 0.f, 0.f);
    else               v = make_float4(0.f, 0.f, 0.f, 0.f);
    store4h(v, &g_A1[(size_t)n * KP1 + j]);
}

__global__ void conv_B_kernel(const float* __restrict__ W, const float* __restrict__ root,
                              int K, int Kp, __half* __restrict__ B) {
    int idx = blockIdx.x * blockDim.x + threadIdx.x;
    if (idx >= 512 * Kp) return;
    int nc = idx / Kp;
    int k  = idx - nc * Kp;
    int s  = nc >> 7;
    int n  = nc & 127;
    float v = 0.f;
    if (k < K) v = (s < 3) ? W[((size_t)s * K + k) * 128 + n] : root[(size_t)k * 128 + n];
    B[idx] = __float2half_rn(v);
}

// ---------------- tensor-core GEMM v5: fp16 single-pass, 4-stage pipeline --------------
__device__ __forceinline__ void cp16(uint32_t dst, const void* src) {
    asm volatile("cp.async.cg.shared.global [%0], [%1], 16;" :: "r"(dst), "l"(src));
}

__device__ __forceinline__ void mma_f16(float* c, const uint32_t* a, uint32_t b0, uint32_t b1) {
    asm volatile(
        "mma.sync.aligned.m16n8k16.row.col.f32.f16.f16.f32 "
        "{%0,%1,%2,%3}, {%4,%5,%6,%7}, {%8,%9}, {%0,%1,%2,%3};"
        : "+f"(c[0]), "+f"(c[1]), "+f"(c[2]), "+f"(c[3])
        : "r"(a[0]), "r"(a[1]), "r"(a[2]), "r"(a[3]), "r"(b0), "r"(b1));
}

__device__ __forceinline__ void ldmx4(uint32_t* r, uint32_t addr) {
    asm volatile("ldmatrix.sync.aligned.m8n8.x4.shared.b16 {%0,%1,%2,%3}, [%4];"
                 : "=r"(r[0]), "=r"(r[1]), "=r"(r[2]), "=r"(r[3]) : "r"(addr));
}

__global__ void __launch_bounds__(256, 2) gemm_tc_kernel(
    const __half* __restrict__ A,
    int Kp, int KT,
    const __half* __restrict__ B,
    const float* __restrict__ bias,
    __half* __restrict__ Yh,            // y sections [3, N, 128] fp16
    float* __restrict__ H)              // h section  [N, 128] fp32
{
    extern __shared__ __align__(16) __half smem[];

    const int tid  = threadIdx.x;
    const int wid  = tid >> 5;
    const int lane = tid & 31;
    const int wm   = wid & 3;
    const int wn   = wid >> 2;
    const int m0   = blockIdx.x * 128;
    const int sec  = blockIdx.y;
    const int nrow0 = sec * 128;

    const uint32_t s_u32 = (uint32_t)__cvta_generic_to_shared(smem);

    float c[2][4][2][4] = {};

    auto load_chunk = [&](int ks, int slot) {
        const int k0 = ks * 16;
        // A plane: 256 16B-chunks (128 rows x 2 halves), one per thread
        {
            int rr    = tid >> 1;
            int half_ = tid & 1;
            if (m0 + rr < NN) {
                const __half* src = A + (size_t)(m0 + rr) * Kp + k0 + half_ * 8;
                uint32_t dst = s_u32 + ((slot * STG_EL + rr * 24 + half_ * 8) << 1);
                cp16(dst, src);
            }
        }
        // B plane: 256 chunks, one per thread
        {
            int rr    = tid >> 1;
            int half_ = tid & 1;
            const __half* src = B + (size_t)(nrow0 + rr) * Kp + k0 + half_ * 8;
            uint32_t dst = s_u32 + ((slot * STG_EL + PLANE + rr * 24 + half_ * 8) << 1);
            cp16(dst, src);
        }
        asm volatile("cp.async.commit_group;" ::: "memory");
    };

    #pragma unroll
    for (int s = 0; s < STAGES - 1; s++) load_chunk(s, s);

    const int bgrp = lane >> 3;
    const int brow = lane & 7;
    const int bn_off = (bgrp & 2) ? 8 : 0;
    const int bk_off = (bgrp & 1) * 8;

    for (int ks = 0; ks < KT; ks++) {
        asm volatile("cp.async.wait_group %0;" :: "n"(STAGES - 2) : "memory");
        __syncthreads();

        const int nk = ks + STAGES - 1;
        if (nk < KT) load_chunk(nk, nk % STAGES);
        else asm volatile("cp.async.commit_group;" ::: "memory");

        const int slot = ks % STAGES;
        const uint32_t st_base = s_u32 + ((slot * STG_EL) << 1);

        uint32_t ah[2][4];
        #pragma unroll
        for (int mt = 0; mt < 2; mt++) {
            int row = wm * 32 + mt * 16 + (lane & 15);
            int cof = (lane >> 4) * 8;
            ldmx4(ah[mt], st_base + ((row * 24 + cof) << 1));
        }

        #pragma unroll
        for (int ntp = 0; ntp < 4; ntp++) {
            const int n = wn * 64 + ntp * 16 + bn_off + brow;
            uint32_t bh[4];
            ldmx4(bh, st_base + ((PLANE + n * 24 + bk_off) << 1));
            #pragma unroll
            for (int mt = 0; mt < 2; mt++) {
                mma_f16(c[mt][ntp][0], ah[mt], bh[0], bh[1]);
                mma_f16(c[mt][ntp][1], ah[mt], bh[2], bh[3]);
            }
        }
    }

    // epilogue
    if (sec < 3) {
        __half* Ysec = Yh + (size_t)sec * NN * HID;
        #pragma unroll
        for (int mt = 0; mt < 2; mt++) {
            int row = m0 + wm * 32 + mt * 16 + (lane >> 2);
            #pragma unroll
            for (int ntp = 0; ntp < 4; ntp++) {
                #pragma unroll
                for (int ng = 0; ng < 2; ng++) {
                    int col = wn * 64 + ntp * 16 + ng * 8 + (lane & 3) * 2;
                    const float* cc = c[mt][ntp][ng];
                    if (row < NN)
                        *reinterpret_cast<__half2*>(Ysec + (size_t)row * HID + col) =
                            __floats2half2_rn(cc[0], cc[1]);
                    if (row + 8 < NN)
                        *reinterpret_cast<__half2*>(Ysec + (size_t)(row + 8) * HID + col) =
                            __floats2half2_rn(cc[2], cc[3]);
                }
            }
        }
    } else {
        #pragma unroll
        for (int mt = 0; mt < 2; mt++) {
            int row = m0 + wm * 32 + mt * 16 + (lane >> 2);
            #pragma unroll
            for (int ntp = 0; ntp < 4; ntp++) {
                #pragma unroll
                for (int ng = 0; ng < 2; ng++) {
                    int col = wn * 64 + ntp * 16 + ng * 8 + (lane & 3) * 2;
                    float bx = bias[col], by = bias[col + 1];
                    const float* cc = c[mt][ntp][ng];
                    if (row < NN) {
                        float* p = H + (size_t)row * HID + col;
                        p[0] = cc[0] + bx;
                        p[1] = cc[1] + by;
                    }
                    if (row + 8 < NN) {
                        float* p = H + (size_t)(row + 8) * HID + col;
                        p[0] = cc[2] + bx;
                        p[1] = cc[3] + by;
                    }
                }
            }
        }
    }
}

// ---------------- CSR gather aggregation (fp16 y) --------------------------------------
template <int LAYER>
__global__ void aggregate_kernel(const int* __restrict__ batch,
                                 const __half* __restrict__ Yh,
                                 const float* __restrict__ H) {
    const int w = (blockIdx.x * blockDim.x + threadIdx.x) >> 5;
    if (w >= NN) return;
    const int lane = threadIdx.x & 31;

    float4 acc = *reinterpret_cast<const float4*>(H + (size_t)w * HID + lane * 4);

    #pragma unroll
    for (int r = 0; r < RR; r++) {
        const int seg = r * NN + w;
        const int s0  = g_off[seg];
        const int c   = g_cnt[seg];
        const float sc = g_inv[seg];
        const __half* Yr = Yh + (size_t)r * NN * HID;
        float4 t = make_float4(0.f, 0.f, 0.f, 0.f);
        int nxt = (c > 0) ? g_csr[s0] : 0;
        for (int i = 0; i < c; i++) {
            int cur = nxt;
            if (i + 1 < c) nxt = g_csr[s0 + i + 1];
            uint2 raw = *reinterpret_cast<const uint2*>(
                Yr + (size_t)cur * HID + lane * 4);
            float2 a = __half22float2(*reinterpret_cast<const __half2*>(&raw.x));
            float2 b = __half22float2(*reinterpret_cast<const __half2*>(&raw.y));
            t.x += a.x; t.y += a.y; t.z += b.x; t.w += b.y;
        }
        acc.x += t.x * sc; acc.y += t.y * sc; acc.z += t.z * sc; acc.w += t.w * sc;
    }

    acc.x = fmaxf(acc.x, 0.f); acc.y = fmaxf(acc.y, 0.f);
    acc.z = fmaxf(acc.z, 0.f); acc.w = fmaxf(acc.w, 0.f);

    if (LAYER == 1) {
        store4h(acc, &g_A2[(size_t)w * KP2 + lane * 4]);
    } else {
        const int g = batch[w];
        float* o = g_pool + (size_t)g * HID + lane * 4;
        asm volatile("red.global.add.v4.f32 [%0], {%1, %2, %3, %4};"
                     :: "l"(o), "f"(acc.x), "f"(acc.y), "f"(acc.z), "f"(acc.w) : "memory");
        if (lane == 0) atomicAdd(&g_gcnt[g], 1);
    }
}

__global__ void final_kernel(const float* __restrict__ lw, const float* __restrict__ lb,
                             float* __restrict__ out) {
    int g = blockIdx.x * blockDim.x + threadIdx.x;
    if (g >= GG) return;
    const int c = g_gcnt[g];
    const float inv = 1.f / (float)(c > 0 ? c : 1);
    float a0 = 0.f, a1 = 0.f, a2 = 0.f, a3 = 0.f;
    const float* p = g_pool + (size_t)g * HID;
    #pragma unroll 8
    for (int k = 0; k < HID; k++) {
        float v = p[k] * inv;
        a0 += v * lw[k * 4 + 0];
        a1 += v * lw[k * 4 + 1];
        a2 += v * lw[k * 4 + 2];
        a3 += v * lw[k * 4 + 3];
    }
    out[g * 4 + 0] = a0 + lb[0];
    out[g * 4 + 1] = a1 + lb[1];
    out[g * 4 + 2] = a2 + lb[2];
    out[g * 4 + 3] = a3 + lb[3];
}

// ---------------- launch ----------------------------------------------------------------
extern "C" void kernel_launch(void* const* d_in, const int* in_sizes, int n_in,
                              void* d_out, int out_size) {
    const float* pos      = (const float*)d_in[0];
    const int*   shape_id = (const int*)  d_in[1];
    const int*   color_id = (const int*)  d_in[2];
    const int*   ei       = (const int*)  d_in[3];
    const int*   et       = (const int*)  d_in[4];
    const int*   batch    = (const int*)  d_in[5];
    const float* se       = (const float*)d_in[6];
    const float* ce       = (const float*)d_in[7];
    const float* W1       = (const float*)d_in[8];
    const float* root1    = (const float*)d_in[9];
    const float* b1       = (const float*)d_in[10];
    const float* W2       = (const float*)d_in[11];
    const float* root2    = (const float*)d_in[12];
    const float* b2       = (const float*)d_in[13];
    const float* lin_w    = (const float*)d_in[14];
    const float* lin_b    = (const float*)d_in[15];
    float* out = (float*)d_out;

    __half *A1, *A2, *B1, *B2, *Y1h, *Y2h;
    float *H1, *H2;
    cudaGetSymbolAddress((void**)&A1, g_A1);
    cudaGetSymbolAddress((void**)&A2, g_A2);
    cudaGetSymbolAddress((void**)&B1, g_B1);
    cudaGetSymbolAddress((void**)&B2, g_B2);
    cudaGetSymbolAddress((void**)&Y1h, g_Y1h);
    cudaGetSymbolAddress((void**)&Y2h, g_Y2h);
    cudaGetSymbolAddress((void**)&H1, g_H1);
    cudaGetSymbolAddress((void**)&H2, g_H2);

    static cudaStream_t s2 = nullptr;
    static cudaEvent_t evFork = nullptr, evJoin = nullptr;
    if (s2 == nullptr) {
        cudaFuncSetAttribute(gemm_tc_kernel,
                             cudaFuncAttributeMaxDynamicSharedMemorySize, SMEM_BYTES);
        cudaStreamCreateWithFlags(&s2, cudaStreamNonBlocking);
        cudaEventCreateWithFlags(&evFork, cudaEventDisableTiming);
        cudaEventCreateWithFlags(&evJoin, cudaEventDisableTiming);
    }

    const int TB = 256;
    dim3 gemm_grid((NN + 127) / 128, 4);

    // Fork side-stream for the CSR build (independent of GEMM layer 1).
    cudaEventRecord(evFork, 0);
    cudaStreamWaitEvent(s2, evFork, 0);

    // main stream: features/weights -> gemm1 (launch idx 3 for ncu)
    build_x1_kernel<<<(NN * (KP1 / 4) + TB - 1) / TB, TB>>>(pos, shape_id, color_id, se, ce);
    conv_B_kernel<<<(512 * KP1 + TB - 1) / TB, TB>>>(W1, root1, K1, KP1, B1);
    conv_B_kernel<<<(512 * KP2 + TB - 1) / TB, TB>>>(W2, root2, K2, KP2, B2);
    gemm_tc_kernel<<<gemm_grid, 256, SMEM_BYTES>>>(A1, KP1, KP1 / 16, B1, b1, Y1h, H1);

    // side stream: CSR build
    zero_misc_kernel<<<(SEG + TB - 1) / TB, TB, 0, s2>>>();
    count_edges_kernel<<<(NE + TB - 1) / TB, TB, 0, s2>>>(ei, et);
    scan1_kernel<<<NBLK, SCAN_T, 0, s2>>>();
    scan2_kernel<<<1, SCAN_T, 0, s2>>>();
    scan3_kernel<<<(SEG + TB - 1) / TB, TB, 0, s2>>>();
    fill_csr_kernel<<<(NE + TB - 1) / TB, TB, 0, s2>>>(ei, et);
    cudaEventRecord(evJoin, s2);
    cudaStreamWaitEvent(0, evJoin, 0);

    // join: rest of the chain on main stream
    aggregate_kernel<1><<<(NN * 32 + TB - 1) / TB, TB>>>(batch, Y1h, H1);
    gemm_tc_kernel<<<gemm_grid, 256, SMEM_BYTES>>>(A2, KP2, KP2 / 16, B2, b2, Y2h, H2);
    aggregate_kernel<2><<<(NN * 32 + TB - 1) / TB, TB>>>(batch, Y2h, H2);
    final_kernel<<<(GG + TB - 1) / TB, TB>>>(lin_w, lin_b, out);
}